// round 8
// baseline (speedup 1.0000x reference)
#include <cuda_runtime.h>
#include <cuda_bf16.h>
#include <cstdint>
#include <math.h>

// ---------------- problem constants ----------------
#define B_SZ      16384
#define KDIM      1024
#define OUT_DIM   1000
#define N_INT     1023
#define DEPTH     10
#define LAMBDA    1e-3f

// ---------------- scratch (device globals) ----------------
__device__ __nv_bfloat16 g_Xhi[(size_t)B_SZ * KDIM];
__device__ __nv_bfloat16 g_Xlo[(size_t)B_SZ * KDIM];
__device__ __nv_bfloat16 g_Phi[(size_t)B_SZ * KDIM];
__device__ __nv_bfloat16 g_Plo[(size_t)B_SZ * KDIM];
__device__ __nv_bfloat16 g_Whi[(size_t)KDIM * KDIM];
__device__ __nv_bfloat16 g_Wlo[(size_t)KDIM * KDIM];
__device__ __nv_bfloat16 g_Lhi[(size_t)KDIM * KDIM];
__device__ __nv_bfloat16 g_Llo[(size_t)KDIM * KDIM];
__device__ float g_s[(size_t)B_SZ * KDIM];
__device__ float g_bias[KDIM];
__device__ float g_T[1023];
__device__ float g_U[2046];

// ---------------- PTX helpers (sm_80-class features only) ----------------
__device__ __forceinline__ uint32_t smem_u32(const void* p) {
    uint32_t a;
    asm("{ .reg .u64 t; cvta.to.shared.u64 t, %1; cvt.u32.u64 %0, t; }" : "=r"(a) : "l"(p));
    return a;
}

#define CP_ASYNC16(dst, src) \
    asm volatile("cp.async.cg.shared.global [%0], [%1], 16;" :: "r"(dst), "l"(src))
#define CP_COMMIT() asm volatile("cp.async.commit_group;" ::: "memory")
#define CP_WAIT(n)  asm volatile("cp.async.wait_group %0;" :: "n"(n) : "memory")

#define LDMX4(r0, r1, r2, r3, addr) \
    asm volatile("ldmatrix.sync.aligned.m8n8.x4.shared.b16 {%0,%1,%2,%3}, [%4];" \
        : "=r"(r0), "=r"(r1), "=r"(r2), "=r"(r3) : "r"(addr))

#define MMA16816(d, a, b) \
    asm volatile("mma.sync.aligned.m16n8k16.row.col.f32.bf16.bf16.f32 " \
        "{%0,%1,%2,%3}, {%4,%5,%6,%7}, {%8,%9}, {%0,%1,%2,%3};" \
        : "+f"((d)[0]), "+f"((d)[1]), "+f"((d)[2]), "+f"((d)[3]) \
        : "r"((a)[0]), "r"((a)[1]), "r"((a)[2]), "r"((a)[3]), \
          "r"((b)[0]), "r"((b)[1]))

// SW64-style bank swizzle for 64B rows: toggles bits 4-5 by row bits 1-2.
// 8 consecutive rows -> distinct 16B banks for any fixed column quarter.
__device__ __forceinline__ uint32_t sw64(uint32_t off) {
    return off ^ ((off >> 3) & 0x30);
}

// ---------------- fp32 -> bf16 hi/lo split ----------------
__device__ __forceinline__ void split2(float x, __nv_bfloat16& h, __nv_bfloat16& l) {
    h = __float2bfloat16(x);
    l = __float2bfloat16(x - __bfloat162float(h));
}

__global__ void split_x_kernel(const float* __restrict__ src,
                               __nv_bfloat16* __restrict__ hi,
                               __nv_bfloat16* __restrict__ lo) {
    size_t i = (size_t)blockIdx.x * blockDim.x + threadIdx.x;  // quad index
    float4 v = ((const float4*)src)[i];
    __nv_bfloat16 h0, h1, h2, h3, l0, l1, l2, l3;
    split2(v.x, h0, l0); split2(v.y, h1, l1); split2(v.z, h2, l2); split2(v.w, h3, l3);
    ((__nv_bfloat162*)hi)[2 * i]     = __nv_bfloat162(h0, h1);
    ((__nv_bfloat162*)hi)[2 * i + 1] = __nv_bfloat162(h2, h3);
    ((__nv_bfloat162*)lo)[2 * i]     = __nv_bfloat162(l0, l1);
    ((__nv_bfloat162*)lo)[2 * i + 1] = __nv_bfloat162(l2, l3);
}

// also zeroes the T/U accumulators
__global__ void repack_w_kernel(const float* __restrict__ Wi,
                                __nv_bfloat16* __restrict__ hi,
                                __nv_bfloat16* __restrict__ lo,
                                float* __restrict__ bias,
                                float* __restrict__ t, float* __restrict__ u) {
    int idx = blockIdx.x * blockDim.x + threadIdx.x;
    if (idx < KDIM * KDIM) {
        int n = idx >> 10, k = idx & 1023;
        float v = (n < N_INT) ? Wi[(size_t)n * 1025 + 1 + k] : 0.0f;
        __nv_bfloat16 h, l; split2(v, h, l);
        hi[idx] = h; lo[idx] = l;
    }
    if (idx < KDIM) bias[idx] = (idx < N_INT) ? Wi[(size_t)idx * 1025] : 0.0f;
    if (idx < 1023) t[idx] = 0.0f;
    if (idx < 2046) u[idx] = 0.0f;
}

__global__ void repack_l_kernel(const float* __restrict__ Wl,
                                __nv_bfloat16* __restrict__ hi,
                                __nv_bfloat16* __restrict__ lo) {
    int idx = blockIdx.x * blockDim.x + threadIdx.x;
    if (idx < KDIM * KDIM) {
        int n = idx >> 10, k = idx & 1023;
        float v = (n < OUT_DIM) ? Wl[(size_t)n * KDIM + k] : 0.0f;
        __nv_bfloat16 h, l; split2(v, h, l);
        hi[idx] = h; lo[idx] = l;
    }
}

// ---------------- mma.sync GEMM: C[M,N] = A * B^T (3-term bf16 emulation) ---
// CTA tile 128x128, BK=32, 3-stage cp.async ring with swizzled 64B rows,
// 256 threads (8 warps 4Mx2N, warp tile 32x64), 2 CTAs/SM.
// One __syncthreads per chunk; prefetch distance = 2 chunks.
#define ROWB        64                    // 64B data, XOR swizzle (no pad)
#define TROWS       128
#define OFF_AHI     0
#define OFF_ALO     (TROWS * ROWB)        // 8192
#define OFF_BHI     (2 * TROWS * ROWB)    // 16384
#define OFF_BLO     (3 * TROWS * ROWB)    // 24576
#define STAGE_BYTES (4 * TROWS * ROWB)    // 32768
#define NSTAGE      3
#define NCHUNK      32                    // K=1024 / BK=32
#define DYN_SMEM    (NSTAGE * STAGE_BYTES + 512)

__device__ __forceinline__ void load_stage(
        const __nv_bfloat16* __restrict__ Ahi, const __nv_bfloat16* __restrict__ Alo,
        const __nv_bfloat16* __restrict__ Bhi, const __nv_bfloat16* __restrict__ Blo,
        int m0, int n0, int chunk, uint32_t sb, int tid) {
    const int r = tid >> 2;            // 0..63
    const int c = tid & 3;             // 16B quarter of the 64B row
    const int kk = chunk * 32 + c * 8; // bf16 element offset
#pragma unroll
    for (int h = 0; h < 2; h++) {
        const int rr = r + h * 64;
        const uint32_t sw = sw64((uint32_t)rr * ROWB + (uint32_t)c * 16);
        const uint32_t d = sb + sw;
        CP_ASYNC16(d + OFF_AHI, Ahi + (size_t)(m0 + rr) * KDIM + kk);
        CP_ASYNC16(d + OFF_ALO, Alo + (size_t)(m0 + rr) * KDIM + kk);
        CP_ASYNC16(d + OFF_BHI, Bhi + (size_t)(n0 + rr) * KDIM + kk);
        CP_ASYNC16(d + OFF_BLO, Blo + (size_t)(n0 + rr) * KDIM + kk);
    }
}

template<bool SIG>
__global__ void __launch_bounds__(256, 2)
mma_gemm_kernel(const __nv_bfloat16* __restrict__ Ahi, const __nv_bfloat16* __restrict__ Alo,
                const __nv_bfloat16* __restrict__ Bhi, const __nv_bfloat16* __restrict__ Blo,
                const float* __restrict__ bias, float* __restrict__ C,
                int ldc, int nclip) {
    extern __shared__ char sm[];
    const uint32_t s0 = smem_u32(sm);
    float* bias_sh = (float*)(sm + NSTAGE * STAGE_BYTES);

    const int tid  = threadIdx.x;
    const int lane = tid & 31;
    const int wid  = tid >> 5;
    const int wm   = wid & 3;    // 4 M-warps of 32 rows
    const int wn   = wid >> 2;   // 2 N-warps of 64 cols
    const int m0   = blockIdx.y * 128;
    const int n0   = blockIdx.x * 128;

    if (SIG && tid < 128) bias_sh[tid] = bias[n0 + tid];

    float acc[2][8][4];
#pragma unroll
    for (int mi = 0; mi < 2; mi++)
#pragma unroll
        for (int ni = 0; ni < 8; ni++)
#pragma unroll
            for (int j = 0; j < 4; j++) acc[mi][ni][j] = 0.0f;

    // per-thread row / column-quarter components for ldmatrix addressing
    const int a_row  = wm * 32 + (lane & 15);        // + mi*16
    const int a_colq = (lane >> 4) * 16;             // + ks*32
    const int b_row  = wn * 64 + ((lane >> 4) & 1) * 8 + (lane & 7);  // + pj*16
    const int b_colq = ((lane >> 3) & 1) * 16;       // + ks*32

    // prologue: stages 0,1
    load_stage(Ahi, Alo, Bhi, Blo, m0, n0, 0, s0, tid);               CP_COMMIT();
    load_stage(Ahi, Alo, Bhi, Blo, m0, n0, 1, s0 + STAGE_BYTES, tid); CP_COMMIT();

    for (int s = 0; s < NCHUNK; s++) {
        if (s < NCHUNK - 1) CP_WAIT(1);   // stage s landed; fresher group may remain
        else                CP_WAIT(0);
        __syncthreads();                  // stage s visible CTA-wide; stage s-1 consumed

        if (s + 2 < NCHUNK) {             // prefetch stage s+2 into slot (s-1)%3
            load_stage(Ahi, Alo, Bhi, Blo, m0, n0, s + 2,
                       s0 + (uint32_t)((s + 2) % 3) * STAGE_BYTES, tid);
            CP_COMMIT();
        }

        const uint32_t sb = s0 + (uint32_t)(s % 3) * STAGE_BYTES;

#pragma unroll
        for (int ks = 0; ks < 2; ks++) {
            uint32_t ah[2][4], al[2][4];
#pragma unroll
            for (int mi = 0; mi < 2; mi++) {
                const uint32_t ao = sb + sw64((uint32_t)(a_row + mi * 16) * ROWB
                                              + (uint32_t)(a_colq + ks * 32));
                LDMX4(ah[mi][0], ah[mi][1], ah[mi][2], ah[mi][3], ao + OFF_AHI);
                LDMX4(al[mi][0], al[mi][1], al[mi][2], al[mi][3], ao + OFF_ALO);
            }
#pragma unroll
            for (int half = 0; half < 2; half++) {
                uint32_t bh[4][2], bl[4][2];
#pragma unroll
                for (int p = 0; p < 2; p++) {
                    const int pj = half * 2 + p;
                    const uint32_t bo = sb + sw64((uint32_t)(b_row + pj * 16) * ROWB
                                                  + (uint32_t)(b_colq + ks * 32));
                    LDMX4(bh[2 * p][0], bh[2 * p][1], bh[2 * p + 1][0], bh[2 * p + 1][1],
                          bo + OFF_BHI);
                    LDMX4(bl[2 * p][0], bl[2 * p][1], bl[2 * p + 1][0], bl[2 * p + 1][1],
                          bo + OFF_BLO);
                }
#pragma unroll
                for (int mi = 0; mi < 2; mi++)
#pragma unroll
                    for (int nj = 0; nj < 4; nj++) {
                        float* a4 = acc[mi][half * 4 + nj];
                        MMA16816(a4, ah[mi], bh[nj]);
                        MMA16816(a4, ah[mi], bl[nj]);
                        MMA16816(a4, al[mi], bh[nj]);
                    }
            }
        }
    }

    // epilogue: direct register -> global stores (float2, 8B aligned)
    const int tr = lane >> 2;
    const int tc = (lane & 3) * 2;
#pragma unroll
    for (int mi = 0; mi < 2; mi++) {
#pragma unroll
        for (int ni = 0; ni < 8; ni++) {
            const int row = m0 + wm * 32 + mi * 16 + tr;
            const int col = n0 + wn * 64 + ni * 8 + tc;
            float v0 = acc[mi][ni][0], v1 = acc[mi][ni][1];
            float v2 = acc[mi][ni][2], v3 = acc[mi][ni][3];
            if (SIG) {
                const float b0 = bias_sh[col - n0];
                const float b1 = bias_sh[col - n0 + 1];
                v0 = 1.0f / (1.0f + expf(-(v0 + b0)));
                v1 = 1.0f / (1.0f + expf(-(v1 + b1)));
                v2 = 1.0f / (1.0f + expf(-(v2 + b0)));
                v3 = 1.0f / (1.0f + expf(-(v3 + b1)));
            }
            if (col < nclip) {  // col even, nclip even -> pair never straddles
                *(float2*)&C[(size_t)row * ldc + col]       = make_float2(v0, v1);
                *(float2*)&C[(size_t)(row + 8) * ldc + col] = make_float2(v2, v3);
            }
        }
    }
}

// ---------------- path + regularizer partial sums ----------------
#define SAMPLES_PER_BLOCK 16

__global__ void __launch_bounds__(256)
path_kernel(const float* __restrict__ s_g,
            __nv_bfloat16* __restrict__ phi, __nv_bfloat16* __restrict__ plo,
            float* __restrict__ gT, float* __restrict__ gU) {
    __shared__ float s_sh[1024];
    __shared__ float bufA[1024];
    __shared__ float bufB[1024];
    __shared__ float Tacc[1023];
    __shared__ float Uacc[2046];

    const int tid = threadIdx.x;
    for (int i = tid; i < 1023; i += 256) Tacc[i] = 0.0f;
    for (int i = tid; i < 2046; i += 256) Uacc[i] = 0.0f;

    const int base = blockIdx.x * SAMPLES_PER_BLOCK;

    for (int s = 0; s < SAMPLES_PER_BLOCK; s++) {
        const int b = base + s;
        __syncthreads();
        for (int i = tid; i < 1024; i += 256)
            s_sh[i] = s_g[(size_t)b * 1024 + i];
        if (tid == 0) bufA[0] = 1.0f;
        __syncthreads();

        float* cur = bufA;
        float* nxt = bufB;
        int toff = 0, uoff = 0;

#pragma unroll
        for (int d = 0; d < DEPTH; d++) {
            const int nout = 2 << d;
            const int nbase = (1 << d) - 1;
            for (int k = tid; k < nout; k += 256) {
                float sv = s_sh[nbase + (k >> 1)];
                float lp = (k & 1) ? (1.0f - sv) : sv;
                float nk = cur[k >> 1] * lp;
                nxt[k] = nk;
                int p = k >> 1;
                float svp = s_sh[nbase + (p >> 1)];
                float lpp = (p & 1) ? (1.0f - svp) : svp;
                float pn = cur[p >> 1] * lpp;
                Uacc[uoff + k] += lp * pn;
                if (k < (nout >> 1)) Tacc[toff + k] += nk;
            }
            __syncthreads();
            toff += nout >> 1;
            uoff += nout;
            float* t = cur; cur = nxt; nxt = t;
        }

        for (int l = tid; l < 1024; l += 256) {
            float p = cur[l];
            __nv_bfloat16 h, lo; split2(p, h, lo);
            phi[(size_t)b * 1024 + l] = h;
            plo[(size_t)b * 1024 + l] = lo;
        }
    }

    __syncthreads();
    for (int i = tid; i < 1023; i += 256) atomicAdd(&gT[i], Tacc[i]);
    for (int i = tid; i < 2046; i += 256) atomicAdd(&gU[i], Uacc[i]);
}

// ---------------- regularizer scalar ----------------
__global__ void reg_kernel(const float* __restrict__ gT, const float* __restrict__ gU,
                           float* __restrict__ out) {
    float local = 0.0f;
    int toff = 0, uoff = 0;
#pragma unroll
    for (int d = 0; d < DEPTH; d++) {
        const int nout = 2 << d;
        const float factor = LAMBDA * exp2f(-(float)d);
        for (int k = threadIdx.x; k < nout; k += 256) {
            float den = gT[toff + (k >> 1)] + 1e-8f;
            float alpha = gU[uoff + k] / den;
            local += factor * (-0.5f) * (logf(alpha) + logf(1.0f - alpha));
        }
        toff += (1 << d);
        uoff += nout;
    }
    __shared__ float red[256];
    red[threadIdx.x] = local;
    __syncthreads();
    for (int s = 128; s > 0; s >>= 1) {
        if (threadIdx.x < s) red[threadIdx.x] += red[threadIdx.x + s];
        __syncthreads();
    }
    if (threadIdx.x == 0) out[0] = red[0];
}

// ---------------- launch ----------------
extern "C" void kernel_launch(void* const* d_in, const int* in_sizes, int n_in,
                              void* d_out, int out_size) {
    const float* X  = (const float*)d_in[0];   // [16384, 1024]
    const float* Wi = (const float*)d_in[1];   // [1023, 1025]
    const float* Wl = (const float*)d_in[2];   // [1000, 1024]
    float* out = (float*)d_out;

    __nv_bfloat16 *xhi, *xlo, *phip, *plop, *whi, *wlo, *lhi, *llo;
    float *s_p, *bias_p, *t_p, *u_p;
    cudaGetSymbolAddress((void**)&xhi,  g_Xhi);
    cudaGetSymbolAddress((void**)&xlo,  g_Xlo);
    cudaGetSymbolAddress((void**)&phip, g_Phi);
    cudaGetSymbolAddress((void**)&plop, g_Plo);
    cudaGetSymbolAddress((void**)&whi,  g_Whi);
    cudaGetSymbolAddress((void**)&wlo,  g_Wlo);
    cudaGetSymbolAddress((void**)&lhi,  g_Lhi);
    cudaGetSymbolAddress((void**)&llo,  g_Llo);
    cudaGetSymbolAddress((void**)&s_p,  g_s);
    cudaGetSymbolAddress((void**)&bias_p, g_bias);
    cudaGetSymbolAddress((void**)&t_p,  g_T);
    cudaGetSymbolAddress((void**)&u_p,  g_U);

    cudaFuncSetAttribute(mma_gemm_kernel<true>,
                         cudaFuncAttributeMaxDynamicSharedMemorySize, DYN_SMEM);
    cudaFuncSetAttribute(mma_gemm_kernel<false>,
                         cudaFuncAttributeMaxDynamicSharedMemorySize, DYN_SMEM);

    // 1. split inputs into bf16 hi/lo (+ zero T/U inside repack_w)
    split_x_kernel<<<(B_SZ * KDIM / 4 + 255) / 256, 256>>>(X, xhi, xlo);
    repack_w_kernel<<<(KDIM * KDIM + 255) / 256, 256>>>(Wi, whi, wlo, bias_p, t_p, u_p);
    repack_l_kernel<<<(KDIM * KDIM + 255) / 256, 256>>>(Wl, lhi, llo);

    // 2. GEMM1 + bias + sigmoid -> g_s (fp32, ld=1024)
    {
        dim3 grid(8, B_SZ / 128);   // (8, 128)
        mma_gemm_kernel<true><<<grid, 256, DYN_SMEM>>>(
            xhi, xlo, whi, wlo, bias_p, s_p, 1024, 1024);
    }

    // 3. path probs (bf16 hi/lo) + regularizer partial sums
    path_kernel<<<B_SZ / SAMPLES_PER_BLOCK, 256>>>(s_p, phip, plop, t_p, u_p);

    // 4. GEMM2: predictions = path @ W_leaf^T -> d_out (ld=1000, clip 1000)
    {
        dim3 grid(8, B_SZ / 128);
        mma_gemm_kernel<false><<<grid, 256, DYN_SMEM>>>(
            phip, plop, lhi, llo, nullptr, out, OUT_DIM, OUT_DIM);
    }

    // 5. regularizer scalar -> last output element
    reg_kernel<<<1, 256>>>(t_p, u_p, out + (out_size - 1));
}

// round 9
// speedup vs baseline: 1.0231x; 1.0231x over previous
#include <cuda_runtime.h>
#include <cuda_bf16.h>
#include <cstdint>
#include <math.h>

// ---------------- problem constants ----------------
#define B_SZ      16384
#define KDIM      1024
#define OUT_DIM   1000
#define N_INT     1023
#define DEPTH     10
#define LAMBDA    1e-3f

// ---------------- scratch (device globals) ----------------
__device__ __nv_bfloat16 g_Xhi[(size_t)B_SZ * KDIM];
__device__ __nv_bfloat16 g_Xlo[(size_t)B_SZ * KDIM];
__device__ __nv_bfloat16 g_Phi[(size_t)B_SZ * KDIM];
__device__ __nv_bfloat16 g_Plo[(size_t)B_SZ * KDIM];
__device__ __nv_bfloat16 g_Whi[(size_t)KDIM * KDIM];
__device__ __nv_bfloat16 g_Wlo[(size_t)KDIM * KDIM];
__device__ __nv_bfloat16 g_Lhi[(size_t)KDIM * KDIM];
__device__ __nv_bfloat16 g_Llo[(size_t)KDIM * KDIM];
__device__ float g_s[(size_t)B_SZ * KDIM];
__device__ float g_bias[KDIM];
__device__ float g_T[1023];
__device__ float g_U[2046];

// ---------------- PTX helpers (sm_80-class features only) ----------------
__device__ __forceinline__ uint32_t smem_u32(const void* p) {
    uint32_t a;
    asm("{ .reg .u64 t; cvta.to.shared.u64 t, %1; cvt.u32.u64 %0, t; }" : "=r"(a) : "l"(p));
    return a;
}

#define CP_ASYNC16(dst, src) \
    asm volatile("cp.async.cg.shared.global [%0], [%1], 16;" :: "r"(dst), "l"(src))
#define CP_COMMIT() asm volatile("cp.async.commit_group;" ::: "memory")
#define CP_WAIT(n)  asm volatile("cp.async.wait_group %0;" :: "n"(n) : "memory")

#define LDMX4(r0, r1, r2, r3, addr) \
    asm volatile("ldmatrix.sync.aligned.m8n8.x4.shared.b16 {%0,%1,%2,%3}, [%4];" \
        : "=r"(r0), "=r"(r1), "=r"(r2), "=r"(r3) : "r"(addr))

#define MMA16816(d, a, b) \
    asm volatile("mma.sync.aligned.m16n8k16.row.col.f32.bf16.bf16.f32 " \
        "{%0,%1,%2,%3}, {%4,%5,%6,%7}, {%8,%9}, {%0,%1,%2,%3};" \
        : "+f"((d)[0]), "+f"((d)[1]), "+f"((d)[2]), "+f"((d)[3]) \
        : "r"((a)[0]), "r"((a)[1]), "r"((a)[2]), "r"((a)[3]), \
          "r"((b)[0]), "r"((b)[1]))

// ---------------- fp32 -> bf16 hi/lo split ----------------
__device__ __forceinline__ void split2(float x, __nv_bfloat16& h, __nv_bfloat16& l) {
    h = __float2bfloat16(x);
    l = __float2bfloat16(x - __bfloat162float(h));
}

__global__ void split_x_kernel(const float* __restrict__ src,
                               __nv_bfloat16* __restrict__ hi,
                               __nv_bfloat16* __restrict__ lo) {
    size_t i = (size_t)blockIdx.x * blockDim.x + threadIdx.x;  // quad index
    float4 v = ((const float4*)src)[i];
    __nv_bfloat16 h0, h1, h2, h3, l0, l1, l2, l3;
    split2(v.x, h0, l0); split2(v.y, h1, l1); split2(v.z, h2, l2); split2(v.w, h3, l3);
    ((__nv_bfloat162*)hi)[2 * i]     = __nv_bfloat162(h0, h1);
    ((__nv_bfloat162*)hi)[2 * i + 1] = __nv_bfloat162(h2, h3);
    ((__nv_bfloat162*)lo)[2 * i]     = __nv_bfloat162(l0, l1);
    ((__nv_bfloat162*)lo)[2 * i + 1] = __nv_bfloat162(l2, l3);
}

// also zeroes the T/U accumulators
__global__ void repack_w_kernel(const float* __restrict__ Wi,
                                __nv_bfloat16* __restrict__ hi,
                                __nv_bfloat16* __restrict__ lo,
                                float* __restrict__ bias,
                                float* __restrict__ t, float* __restrict__ u) {
    int idx = blockIdx.x * blockDim.x + threadIdx.x;
    if (idx < KDIM * KDIM) {
        int n = idx >> 10, k = idx & 1023;
        float v = (n < N_INT) ? Wi[(size_t)n * 1025 + 1 + k] : 0.0f;
        __nv_bfloat16 h, l; split2(v, h, l);
        hi[idx] = h; lo[idx] = l;
    }
    if (idx < KDIM) bias[idx] = (idx < N_INT) ? Wi[(size_t)idx * 1025] : 0.0f;
    if (idx < 1023) t[idx] = 0.0f;
    if (idx < 2046) u[idx] = 0.0f;
}

__global__ void repack_l_kernel(const float* __restrict__ Wl,
                                __nv_bfloat16* __restrict__ hi,
                                __nv_bfloat16* __restrict__ lo) {
    int idx = blockIdx.x * blockDim.x + threadIdx.x;
    if (idx < KDIM * KDIM) {
        int n = idx >> 10, k = idx & 1023;
        float v = (n < OUT_DIM) ? Wl[(size_t)n * KDIM + k] : 0.0f;
        __nv_bfloat16 h, l; split2(v, h, l);
        hi[idx] = h; lo[idx] = l;
    }
}

// ---------------- mma.sync GEMM: C[M,N] = A * B^T (3-term bf16 emulation) ---
// CTA tile 128x128, BK=32, 2-stage cp.async ring, 256 threads (8 warps 4Mx2N,
// warp tile 32x64), 2 CTAs/SM. ONE __syncthreads per BK=32 chunk. MMAs are
// term-major interleaved so consecutive HMMAs never share an accumulator.
#define ROWB        80                    // 64B data + 16B pad (conflict-free)
#define TROWS       128
#define OFF_AHI     0
#define OFF_ALO     (TROWS * ROWB)        // 10240
#define OFF_BHI     (2 * TROWS * ROWB)    // 20480
#define OFF_BLO     (3 * TROWS * ROWB)    // 30720
#define STAGE_BYTES (4 * TROWS * ROWB)    // 40960
#define NSTAGE      2
#define NCHUNK      32                    // K=1024 / BK=32
#define DYN_SMEM    (NSTAGE * STAGE_BYTES + 512)

__device__ __forceinline__ void load_stage(
        const __nv_bfloat16* __restrict__ Ahi, const __nv_bfloat16* __restrict__ Alo,
        const __nv_bfloat16* __restrict__ Bhi, const __nv_bfloat16* __restrict__ Blo,
        int m0, int n0, int chunk, uint32_t sb, int tid) {
    const int r = tid >> 2;            // 0..63
    const int c = tid & 3;             // 16B quarter of the 64B row
    const int kk = chunk * 32 + c * 8; // bf16 element offset
    const uint32_t doff = (uint32_t)r * ROWB + (uint32_t)c * 16;
#pragma unroll
    for (int h = 0; h < 2; h++) {
        const int rr = r + h * 64;
        const uint32_t d = sb + doff + (uint32_t)(h * 64 * ROWB);
        CP_ASYNC16(d + OFF_AHI, Ahi + (size_t)(m0 + rr) * KDIM + kk);
        CP_ASYNC16(d + OFF_ALO, Alo + (size_t)(m0 + rr) * KDIM + kk);
        CP_ASYNC16(d + OFF_BHI, Bhi + (size_t)(n0 + rr) * KDIM + kk);
        CP_ASYNC16(d + OFF_BLO, Blo + (size_t)(n0 + rr) * KDIM + kk);
    }
}

template<bool SIG>
__global__ void __launch_bounds__(256, 2)
mma_gemm_kernel(const __nv_bfloat16* __restrict__ Ahi, const __nv_bfloat16* __restrict__ Alo,
                const __nv_bfloat16* __restrict__ Bhi, const __nv_bfloat16* __restrict__ Blo,
                const float* __restrict__ bias, float* __restrict__ C,
                int ldc, int nclip) {
    extern __shared__ char sm[];
    const uint32_t s0 = smem_u32(sm);
    float* bias_sh = (float*)(sm + NSTAGE * STAGE_BYTES);

    const int tid  = threadIdx.x;
    const int lane = tid & 31;
    const int wid  = tid >> 5;
    const int wm   = wid & 3;    // 4 M-warps of 32 rows
    const int wn   = wid >> 2;   // 2 N-warps of 64 cols
    const int m0   = blockIdx.y * 128;
    const int n0   = blockIdx.x * 128;

    if (SIG && tid < 128) bias_sh[tid] = bias[n0 + tid];

    float acc[2][8][4];
#pragma unroll
    for (int mi = 0; mi < 2; mi++)
#pragma unroll
        for (int ni = 0; ni < 8; ni++)
#pragma unroll
            for (int j = 0; j < 4; j++) acc[mi][ni][j] = 0.0f;

    // ldmatrix per-thread address components
    const uint32_t a_off = (uint32_t)(wm * 32 + (lane & 15)) * ROWB
                         + (uint32_t)(lane >> 4) * 16;
    const uint32_t b_off = (uint32_t)(wn * 64 + ((lane >> 4) & 1) * 8 + (lane & 7)) * ROWB
                         + (uint32_t)((lane >> 3) & 1) * 16;

    // prologue: stage 0
    load_stage(Ahi, Alo, Bhi, Blo, m0, n0, 0, s0, tid);
    CP_COMMIT();

    for (int s = 0; s < NCHUNK; s++) {
        CP_WAIT(0);          // stage s landed (this thread)
        __syncthreads();     // stage s visible CTA-wide; stage s-1 reads all done

        const uint32_t sb = s0 + (uint32_t)(s & 1) * STAGE_BYTES;

#pragma unroll
        for (int ks = 0; ks < 2; ks++) {
            uint32_t ah[2][4], al[2][4];
#pragma unroll
            for (int mi = 0; mi < 2; mi++) {
                const uint32_t ao = sb + a_off + (uint32_t)(mi * 16 * ROWB)
                                  + (uint32_t)(ks * 32);
                LDMX4(ah[mi][0], ah[mi][1], ah[mi][2], ah[mi][3], ao + OFF_AHI);
                LDMX4(al[mi][0], al[mi][1], al[mi][2], al[mi][3], ao + OFF_ALO);
            }
#pragma unroll
            for (int half = 0; half < 2; half++) {
                uint32_t bh[4][2], bl[4][2];
#pragma unroll
                for (int p = 0; p < 2; p++) {
                    const int pj = half * 2 + p;
                    const uint32_t bo = sb + b_off + (uint32_t)(pj * 16 * ROWB)
                                      + (uint32_t)(ks * 32);
                    LDMX4(bh[2 * p][0], bh[2 * p][1], bh[2 * p + 1][0], bh[2 * p + 1][1],
                          bo + OFF_BHI);
                    LDMX4(bl[2 * p][0], bl[2 * p][1], bl[2 * p + 1][0], bl[2 * p + 1][1],
                          bo + OFF_BLO);
                }
                // term-major: consecutive MMAs always target different
                // accumulators (RAW distance 8 -> HMMA latency hidden by ILP)
#pragma unroll
                for (int t = 0; t < 3; t++)
#pragma unroll
                    for (int mi = 0; mi < 2; mi++)
#pragma unroll
                        for (int nj = 0; nj < 4; nj++) {
                            float* a4 = acc[mi][half * 4 + nj];
                            if (t == 0)      MMA16816(a4, ah[mi], bh[nj]);
                            else if (t == 1) MMA16816(a4, ah[mi], bl[nj]);
                            else             MMA16816(a4, al[mi], bh[nj]);
                        }
            }
            // prefetch next stage between k-steps: latency hides under the
            // remaining ~half-chunk of MMAs.
            if (ks == 0 && s + 1 < NCHUNK) {
                load_stage(Ahi, Alo, Bhi, Blo, m0, n0, s + 1,
                           s0 + (uint32_t)((s + 1) & 1) * STAGE_BYTES, tid);
                CP_COMMIT();
            }
        }
    }

    // epilogue: direct register -> global stores (float2, 8B aligned)
    const int tr = lane >> 2;
    const int tc = (lane & 3) * 2;
#pragma unroll
    for (int mi = 0; mi < 2; mi++) {
#pragma unroll
        for (int ni = 0; ni < 8; ni++) {
            const int row = m0 + wm * 32 + mi * 16 + tr;
            const int col = n0 + wn * 64 + ni * 8 + tc;
            float v0 = acc[mi][ni][0], v1 = acc[mi][ni][1];
            float v2 = acc[mi][ni][2], v3 = acc[mi][ni][3];
            if (SIG) {
                const float b0 = bias_sh[col - n0];
                const float b1 = bias_sh[col - n0 + 1];
                v0 = 1.0f / (1.0f + expf(-(v0 + b0)));
                v1 = 1.0f / (1.0f + expf(-(v1 + b1)));
                v2 = 1.0f / (1.0f + expf(-(v2 + b0)));
                v3 = 1.0f / (1.0f + expf(-(v3 + b1)));
            }
            if (col < nclip) {  // col even, nclip even -> pair never straddles
                *(float2*)&C[(size_t)row * ldc + col]       = make_float2(v0, v1);
                *(float2*)&C[(size_t)(row + 8) * ldc + col] = make_float2(v2, v3);
            }
        }
    }
}

// ---------------- path + regularizer partial sums ----------------
#define SAMPLES_PER_BLOCK 8

__global__ void __launch_bounds__(256)
path_kernel(const float* __restrict__ s_g,
            __nv_bfloat16* __restrict__ phi, __nv_bfloat16* __restrict__ plo,
            float* __restrict__ gT, float* __restrict__ gU) {
    __shared__ float s_sh[1024];
    __shared__ float bufA[1024];
    __shared__ float bufB[1024];
    __shared__ float Tacc[1023];
    __shared__ float Uacc[2046];

    const int tid = threadIdx.x;
    for (int i = tid; i < 1023; i += 256) Tacc[i] = 0.0f;
    for (int i = tid; i < 2046; i += 256) Uacc[i] = 0.0f;

    const int base = blockIdx.x * SAMPLES_PER_BLOCK;

    for (int s = 0; s < SAMPLES_PER_BLOCK; s++) {
        const int b = base + s;
        __syncthreads();
        for (int i = tid; i < 1024; i += 256)
            s_sh[i] = s_g[(size_t)b * 1024 + i];
        if (tid == 0) bufA[0] = 1.0f;
        __syncthreads();

        float* cur = bufA;
        float* nxt = bufB;
        int toff = 0, uoff = 0;

#pragma unroll
        for (int d = 0; d < DEPTH; d++) {
            const int nout = 2 << d;
            const int nbase = (1 << d) - 1;
            for (int k = tid; k < nout; k += 256) {
                float sv = s_sh[nbase + (k >> 1)];
                float lp = (k & 1) ? (1.0f - sv) : sv;
                float nk = cur[k >> 1] * lp;
                nxt[k] = nk;
                int p = k >> 1;
                float svp = s_sh[nbase + (p >> 1)];
                float lpp = (p & 1) ? (1.0f - svp) : svp;
                float pn = cur[p >> 1] * lpp;
                Uacc[uoff + k] += lp * pn;
                if (k < (nout >> 1)) Tacc[toff + k] += nk;
            }
            __syncthreads();
            toff += nout >> 1;
            uoff += nout;
            float* t = cur; cur = nxt; nxt = t;
        }

        for (int l = tid; l < 1024; l += 256) {
            float p = cur[l];
            __nv_bfloat16 h, lo; split2(p, h, lo);
            phi[(size_t)b * 1024 + l] = h;
            plo[(size_t)b * 1024 + l] = lo;
        }
    }

    __syncthreads();
    for (int i = tid; i < 1023; i += 256) atomicAdd(&gT[i], Tacc[i]);
    for (int i = tid; i < 2046; i += 256) atomicAdd(&gU[i], Uacc[i]);
}

// ---------------- regularizer scalar ----------------
__global__ void reg_kernel(const float* __restrict__ gT, const float* __restrict__ gU,
                           float* __restrict__ out) {
    float local = 0.0f;
    int toff = 0, uoff = 0;
#pragma unroll
    for (int d = 0; d < DEPTH; d++) {
        const int nout = 2 << d;
        const float factor = LAMBDA * exp2f(-(float)d);
        for (int k = threadIdx.x; k < nout; k += 256) {
            float den = gT[toff + (k >> 1)] + 1e-8f;
            float alpha = gU[uoff + k] / den;
            local += factor * (-0.5f) * (logf(alpha) + logf(1.0f - alpha));
        }
        toff += (1 << d);
        uoff += nout;
    }
    __shared__ float red[256];
    red[threadIdx.x] = local;
    __syncthreads();
    for (int s = 128; s > 0; s >>= 1) {
        if (threadIdx.x < s) red[threadIdx.x] += red[threadIdx.x + s];
        __syncthreads();
    }
    if (threadIdx.x == 0) out[0] = red[0];
}

// ---------------- launch ----------------
extern "C" void kernel_launch(void* const* d_in, const int* in_sizes, int n_in,
                              void* d_out, int out_size) {
    const float* X  = (const float*)d_in[0];   // [16384, 1024]
    const float* Wi = (const float*)d_in[1];   // [1023, 1025]
    const float* Wl = (const float*)d_in[2];   // [1000, 1024]
    float* out = (float*)d_out;

    __nv_bfloat16 *xhi, *xlo, *phip, *plop, *whi, *wlo, *lhi, *llo;
    float *s_p, *bias_p, *t_p, *u_p;
    cudaGetSymbolAddress((void**)&xhi,  g_Xhi);
    cudaGetSymbolAddress((void**)&xlo,  g_Xlo);
    cudaGetSymbolAddress((void**)&phip, g_Phi);
    cudaGetSymbolAddress((void**)&plop, g_Plo);
    cudaGetSymbolAddress((void**)&whi,  g_Whi);
    cudaGetSymbolAddress((void**)&wlo,  g_Wlo);
    cudaGetSymbolAddress((void**)&lhi,  g_Lhi);
    cudaGetSymbolAddress((void**)&llo,  g_Llo);
    cudaGetSymbolAddress((void**)&s_p,  g_s);
    cudaGetSymbolAddress((void**)&bias_p, g_bias);
    cudaGetSymbolAddress((void**)&t_p,  g_T);
    cudaGetSymbolAddress((void**)&u_p,  g_U);

    cudaFuncSetAttribute(mma_gemm_kernel<true>,
                         cudaFuncAttributeMaxDynamicSharedMemorySize, DYN_SMEM);
    cudaFuncSetAttribute(mma_gemm_kernel<false>,
                         cudaFuncAttributeMaxDynamicSharedMemorySize, DYN_SMEM);

    // 1. split inputs into bf16 hi/lo (+ zero T/U inside repack_w)
    split_x_kernel<<<(B_SZ * KDIM / 4 + 255) / 256, 256>>>(X, xhi, xlo);
    repack_w_kernel<<<(KDIM * KDIM + 255) / 256, 256>>>(Wi, whi, wlo, bias_p, t_p, u_p);
    repack_l_kernel<<<(KDIM * KDIM + 255) / 256, 256>>>(Wl, lhi, llo);

    // 2. GEMM1 + bias + sigmoid -> g_s (fp32, ld=1024)
    {
        dim3 grid(8, B_SZ / 128);   // (8, 128)
        mma_gemm_kernel<true><<<grid, 256, DYN_SMEM>>>(
            xhi, xlo, whi, wlo, bias_p, s_p, 1024, 1024);
    }

    // 3. path probs (bf16 hi/lo) + regularizer partial sums
    path_kernel<<<B_SZ / SAMPLES_PER_BLOCK, 256>>>(s_p, phip, plop, t_p, u_p);

    // 4. GEMM2: predictions = path @ W_leaf^T -> d_out (ld=1000, clip 1000)
    {
        dim3 grid(8, B_SZ / 128);
        mma_gemm_kernel<false><<<grid, 256, DYN_SMEM>>>(
            phip, plop, lhi, llo, nullptr, out, OUT_DIM, OUT_DIM);
    }

    // 5. regularizer scalar -> last output element
    reg_kernel<<<1, 256>>>(t_p, u_p, out + (out_size - 1));
}

// round 10
// speedup vs baseline: 1.3262x; 1.2963x over previous
#include <cuda_runtime.h>
#include <cuda_fp16.h>
#include <cstdint>
#include <math.h>

// ---------------- problem constants ----------------
#define B_SZ      16384
#define KDIM      1024
#define OUT_DIM   1000
#define N_INT     1023
#define DEPTH     10
#define LAMBDA    1e-3f
#define WSCALE    256.0f
#define WSCALE_INV (1.0f / 256.0f)

// ---------------- scratch (device globals) ----------------
__device__ __half g_Xh[(size_t)B_SZ * KDIM];        // X as fp16 (hi only)
__device__ __half g_Ph[(size_t)B_SZ * KDIM];        // path probs fp16
__device__ __half g_Whi[(size_t)KDIM * KDIM];       // W_internal*256 hi
__device__ __half g_Wlo[(size_t)KDIM * KDIM];       // W_internal*256 lo
__device__ __half g_Lhi[(size_t)KDIM * KDIM];       // W_leaf*256 hi
__device__ __half g_Llo[(size_t)KDIM * KDIM];       // W_leaf*256 lo
__device__ float g_s[(size_t)B_SZ * KDIM];
__device__ float g_bias[KDIM];
__device__ float g_T[1023];
__device__ float g_U[2046];

// ---------------- PTX helpers (sm_80-class features only) ----------------
__device__ __forceinline__ uint32_t smem_u32(const void* p) {
    uint32_t a;
    asm("{ .reg .u64 t; cvta.to.shared.u64 t, %1; cvt.u32.u64 %0, t; }" : "=r"(a) : "l"(p));
    return a;
}

#define CP_ASYNC16(dst, src) \
    asm volatile("cp.async.cg.shared.global [%0], [%1], 16;" :: "r"(dst), "l"(src))
#define CP_COMMIT() asm volatile("cp.async.commit_group;" ::: "memory")
#define CP_WAIT(n)  asm volatile("cp.async.wait_group %0;" :: "n"(n) : "memory")

#define LDMX4(r0, r1, r2, r3, addr) \
    asm volatile("ldmatrix.sync.aligned.m8n8.x4.shared.b16 {%0,%1,%2,%3}, [%4];" \
        : "=r"(r0), "=r"(r1), "=r"(r2), "=r"(r3) : "r"(addr))

#define MMAF16(d, a, b) \
    asm volatile("mma.sync.aligned.m16n8k16.row.col.f32.f16.f16.f32 " \
        "{%0,%1,%2,%3}, {%4,%5,%6,%7}, {%8,%9}, {%0,%1,%2,%3};" \
        : "+f"((d)[0]), "+f"((d)[1]), "+f"((d)[2]), "+f"((d)[3]) \
        : "r"((a)[0]), "r"((a)[1]), "r"((a)[2]), "r"((a)[3]), \
          "r"((b)[0]), "r"((b)[1]))

// ---------------- fp32 -> fp16 hi/lo split ----------------
__device__ __forceinline__ void split2h(float x, __half& h, __half& l) {
    h = __float2half_rn(x);
    l = __float2half_rn(x - __half2float(h));
}

// X: plain fp32 -> fp16 conversion (hi only; 2-term scheme drops A-lo)
__global__ void conv_x_kernel(const float* __restrict__ src,
                              __half* __restrict__ dst) {
    size_t i = (size_t)blockIdx.x * blockDim.x + threadIdx.x;  // quad index
    float4 v = ((const float4*)src)[i];
    ((__half2*)dst)[2 * i]     = __floats2half2_rn(v.x, v.y);
    ((__half2*)dst)[2 * i + 1] = __floats2half2_rn(v.z, v.w);
}

// W_internal: repack [1023,1025] -> aligned fp16 hi/lo (x256) + bias; zero T/U
__global__ void repack_w_kernel(const float* __restrict__ Wi,
                                __half* __restrict__ hi,
                                __half* __restrict__ lo,
                                float* __restrict__ bias,
                                float* __restrict__ t, float* __restrict__ u) {
    int idx = blockIdx.x * blockDim.x + threadIdx.x;
    if (idx < KDIM * KDIM) {
        int n = idx >> 10, k = idx & 1023;
        float v = (n < N_INT) ? Wi[(size_t)n * 1025 + 1 + k] * WSCALE : 0.0f;
        __half h, l; split2h(v, h, l);
        hi[idx] = h; lo[idx] = l;
    }
    if (idx < KDIM) bias[idx] = (idx < N_INT) ? Wi[(size_t)idx * 1025] : 0.0f;
    if (idx < 1023) t[idx] = 0.0f;
    if (idx < 2046) u[idx] = 0.0f;
}

__global__ void repack_l_kernel(const float* __restrict__ Wl,
                                __half* __restrict__ hi,
                                __half* __restrict__ lo) {
    int idx = blockIdx.x * blockDim.x + threadIdx.x;
    if (idx < KDIM * KDIM) {
        int n = idx >> 10, k = idx & 1023;
        float v = (n < OUT_DIM) ? Wl[(size_t)n * KDIM + k] * WSCALE : 0.0f;
        __half h, l; split2h(v, h, l);
        hi[idx] = h; lo[idx] = l;
    }
}

// ---------------- mma.sync GEMM: C[M,N] = A * (Bh+Bl)^T, fp16 2-term -------
// CTA tile 128x128, BK=32, 2-stage cp.async ring, 256 threads (8 warps 4Mx2N,
// warp tile 32x64), 2 CTAs/SM. One __syncthreads per BK=32 chunk.
#define ROWB        80                    // 64B data + 16B pad (conflict-free)
#define TROWS       128
#define OFF_AH      0
#define OFF_BH      (TROWS * ROWB)        // 10240
#define OFF_BL      (2 * TROWS * ROWB)    // 20480
#define STAGE_BYTES (3 * TROWS * ROWB)    // 30720
#define NSTAGE      2
#define NCHUNK      32                    // K=1024 / BK=32
#define DYN_SMEM    (NSTAGE * STAGE_BYTES + 512)

__device__ __forceinline__ void load_stage(
        const __half* __restrict__ Ah,
        const __half* __restrict__ Bh, const __half* __restrict__ Bl,
        int m0, int n0, int chunk, uint32_t sb, int tid) {
    const int r = tid >> 2;            // 0..63
    const int c = tid & 3;             // 16B quarter of the 64B row
    const int kk = chunk * 32 + c * 8; // fp16 element offset
    const uint32_t doff = (uint32_t)r * ROWB + (uint32_t)c * 16;
#pragma unroll
    for (int h = 0; h < 2; h++) {
        const int rr = r + h * 64;
        const uint32_t d = sb + doff + (uint32_t)(h * 64 * ROWB);
        CP_ASYNC16(d + OFF_AH, Ah + (size_t)(m0 + rr) * KDIM + kk);
        CP_ASYNC16(d + OFF_BH, Bh + (size_t)(n0 + rr) * KDIM + kk);
        CP_ASYNC16(d + OFF_BL, Bl + (size_t)(n0 + rr) * KDIM + kk);
    }
}

template<bool SIG>
__global__ void __launch_bounds__(256, 2)
mma_gemm_kernel(const __half* __restrict__ Ah,
                const __half* __restrict__ Bh, const __half* __restrict__ Bl,
                const float* __restrict__ bias, float* __restrict__ C,
                int ldc, int nclip) {
    extern __shared__ char sm[];
    const uint32_t s0 = smem_u32(sm);
    float* bias_sh = (float*)(sm + NSTAGE * STAGE_BYTES);

    const int tid  = threadIdx.x;
    const int lane = tid & 31;
    const int wid  = tid >> 5;
    const int wm   = wid & 3;    // 4 M-warps of 32 rows
    const int wn   = wid >> 2;   // 2 N-warps of 64 cols
    const int m0   = blockIdx.y * 128;
    const int n0   = blockIdx.x * 128;

    if (SIG && tid < 128) bias_sh[tid] = bias[n0 + tid];

    float acc[2][8][4];
#pragma unroll
    for (int mi = 0; mi < 2; mi++)
#pragma unroll
        for (int ni = 0; ni < 8; ni++)
#pragma unroll
            for (int j = 0; j < 4; j++) acc[mi][ni][j] = 0.0f;

    // ldmatrix per-thread address components
    const uint32_t a_off = (uint32_t)(wm * 32 + (lane & 15)) * ROWB
                         + (uint32_t)(lane >> 4) * 16;
    const uint32_t b_off = (uint32_t)(wn * 64 + ((lane >> 4) & 1) * 8 + (lane & 7)) * ROWB
                         + (uint32_t)((lane >> 3) & 1) * 16;

    // prologue: stage 0
    load_stage(Ah, Bh, Bl, m0, n0, 0, s0, tid);
    CP_COMMIT();

    for (int s = 0; s < NCHUNK; s++) {
        CP_WAIT(0);          // stage s landed (this thread)
        __syncthreads();     // stage s visible CTA-wide; stage s-1 reads all done

        const uint32_t sb = s0 + (uint32_t)(s & 1) * STAGE_BYTES;

#pragma unroll
        for (int ks = 0; ks < 2; ks++) {
            uint32_t ar[2][4];
#pragma unroll
            for (int mi = 0; mi < 2; mi++) {
                const uint32_t ao = sb + a_off + (uint32_t)(mi * 16 * ROWB)
                                  + (uint32_t)(ks * 32);
                LDMX4(ar[mi][0], ar[mi][1], ar[mi][2], ar[mi][3], ao + OFF_AH);
            }
#pragma unroll
            for (int half = 0; half < 2; half++) {
                uint32_t bh[4][2], bl[4][2];
#pragma unroll
                for (int p = 0; p < 2; p++) {
                    const int pj = half * 2 + p;
                    const uint32_t bo = sb + b_off + (uint32_t)(pj * 16 * ROWB)
                                      + (uint32_t)(ks * 32);
                    LDMX4(bh[2 * p][0], bh[2 * p][1], bh[2 * p + 1][0], bh[2 * p + 1][1],
                          bo + OFF_BH);
                    LDMX4(bl[2 * p][0], bl[2 * p][1], bl[2 * p + 1][0], bl[2 * p + 1][1],
                          bo + OFF_BL);
                }
#pragma unroll
                for (int mi = 0; mi < 2; mi++)
#pragma unroll
                    for (int nj = 0; nj < 4; nj++) {
                        float* a4 = acc[mi][half * 4 + nj];
                        MMAF16(a4, ar[mi], bh[nj]);
                        MMAF16(a4, ar[mi], bl[nj]);
                    }
            }
            // prefetch next stage between k-steps
            if (ks == 0 && s + 1 < NCHUNK) {
                load_stage(Ah, Bh, Bl, m0, n0, s + 1,
                           s0 + (uint32_t)((s + 1) & 1) * STAGE_BYTES, tid);
                CP_COMMIT();
            }
        }
    }

    // epilogue: unscale (weights were x256), bias+sigmoid if SIG
    const int tr = lane >> 2;
    const int tc = (lane & 3) * 2;
#pragma unroll
    for (int mi = 0; mi < 2; mi++) {
#pragma unroll
        for (int ni = 0; ni < 8; ni++) {
            const int row = m0 + wm * 32 + mi * 16 + tr;
            const int col = n0 + wn * 64 + ni * 8 + tc;
            float v0 = acc[mi][ni][0] * WSCALE_INV;
            float v1 = acc[mi][ni][1] * WSCALE_INV;
            float v2 = acc[mi][ni][2] * WSCALE_INV;
            float v3 = acc[mi][ni][3] * WSCALE_INV;
            if (SIG) {
                const float b0 = bias_sh[col - n0];
                const float b1 = bias_sh[col - n0 + 1];
                v0 = 1.0f / (1.0f + expf(-(v0 + b0)));
                v1 = 1.0f / (1.0f + expf(-(v1 + b1)));
                v2 = 1.0f / (1.0f + expf(-(v2 + b0)));
                v3 = 1.0f / (1.0f + expf(-(v3 + b1)));
            }
            if (col < nclip) {  // col even, nclip even -> pair never straddles
                *(float2*)&C[(size_t)row * ldc + col]       = make_float2(v0, v1);
                *(float2*)&C[(size_t)(row + 8) * ldc + col] = make_float2(v2, v3);
            }
        }
    }
}

// ---------------- path + regularizer partial sums ----------------
#define SAMPLES_PER_BLOCK 8

__global__ void __launch_bounds__(256)
path_kernel(const float* __restrict__ s_g,
            __half* __restrict__ ph,
            float* __restrict__ gT, float* __restrict__ gU) {
    __shared__ float s_sh[1024];
    __shared__ float bufA[1024];
    __shared__ float bufB[1024];
    __shared__ float Tacc[1023];
    __shared__ float Uacc[2046];

    const int tid = threadIdx.x;
    for (int i = tid; i < 1023; i += 256) Tacc[i] = 0.0f;
    for (int i = tid; i < 2046; i += 256) Uacc[i] = 0.0f;

    const int base = blockIdx.x * SAMPLES_PER_BLOCK;

    for (int s = 0; s < SAMPLES_PER_BLOCK; s++) {
        const int b = base + s;
        __syncthreads();
        for (int i = tid; i < 1024; i += 256)
            s_sh[i] = s_g[(size_t)b * 1024 + i];
        if (tid == 0) bufA[0] = 1.0f;
        __syncthreads();

        float* cur = bufA;
        float* nxt = bufB;
        int toff = 0, uoff = 0;

#pragma unroll
        for (int d = 0; d < DEPTH; d++) {
            const int nout = 2 << d;
            const int nbase = (1 << d) - 1;
            for (int k = tid; k < nout; k += 256) {
                float sv = s_sh[nbase + (k >> 1)];
                float lp = (k & 1) ? (1.0f - sv) : sv;
                float nk = cur[k >> 1] * lp;
                nxt[k] = nk;
                int p = k >> 1;
                float svp = s_sh[nbase + (p >> 1)];
                float lpp = (p & 1) ? (1.0f - svp) : svp;
                float pn = cur[p >> 1] * lpp;
                Uacc[uoff + k] += lp * pn;
                if (k < (nout >> 1)) Tacc[toff + k] += nk;
            }
            __syncthreads();
            toff += nout >> 1;
            uoff += nout;
            float* t = cur; cur = nxt; nxt = t;
        }

        for (int l = tid; l < 1024; l += 256)
            ph[(size_t)b * 1024 + l] = __float2half_rn(cur[l]);
    }

    __syncthreads();
    for (int i = tid; i < 1023; i += 256) atomicAdd(&gT[i], Tacc[i]);
    for (int i = tid; i < 2046; i += 256) atomicAdd(&gU[i], Uacc[i]);
}

// ---------------- regularizer scalar ----------------
__global__ void reg_kernel(const float* __restrict__ gT, const float* __restrict__ gU,
                           float* __restrict__ out) {
    float local = 0.0f;
    int toff = 0, uoff = 0;
#pragma unroll
    for (int d = 0; d < DEPTH; d++) {
        const int nout = 2 << d;
        const float factor = LAMBDA * exp2f(-(float)d);
        for (int k = threadIdx.x; k < nout; k += 256) {
            float den = gT[toff + (k >> 1)] + 1e-8f;
            float alpha = gU[uoff + k] / den;
            local += factor * (-0.5f) * (logf(alpha) + logf(1.0f - alpha));
        }
        toff += (1 << d);
        uoff += nout;
    }
    __shared__ float red[256];
    red[threadIdx.x] = local;
    __syncthreads();
    for (int s = 128; s > 0; s >>= 1) {
        if (threadIdx.x < s) red[threadIdx.x] += red[threadIdx.x + s];
        __syncthreads();
    }
    if (threadIdx.x == 0) out[0] = red[0];
}

// ---------------- launch ----------------
extern "C" void kernel_launch(void* const* d_in, const int* in_sizes, int n_in,
                              void* d_out, int out_size) {
    const float* X  = (const float*)d_in[0];   // [16384, 1024]
    const float* Wi = (const float*)d_in[1];   // [1023, 1025]
    const float* Wl = (const float*)d_in[2];   // [1000, 1024]
    float* out = (float*)d_out;

    __half *xh, *php, *whi, *wlo, *lhi, *llo;
    float *s_p, *bias_p, *t_p, *u_p;
    cudaGetSymbolAddress((void**)&xh,   g_Xh);
    cudaGetSymbolAddress((void**)&php,  g_Ph);
    cudaGetSymbolAddress((void**)&whi,  g_Whi);
    cudaGetSymbolAddress((void**)&wlo,  g_Wlo);
    cudaGetSymbolAddress((void**)&lhi,  g_Lhi);
    cudaGetSymbolAddress((void**)&llo,  g_Llo);
    cudaGetSymbolAddress((void**)&s_p,  g_s);
    cudaGetSymbolAddress((void**)&bias_p, g_bias);
    cudaGetSymbolAddress((void**)&t_p,  g_T);
    cudaGetSymbolAddress((void**)&u_p,  g_U);

    cudaFuncSetAttribute(mma_gemm_kernel<true>,
                         cudaFuncAttributeMaxDynamicSharedMemorySize, DYN_SMEM);
    cudaFuncSetAttribute(mma_gemm_kernel<false>,
                         cudaFuncAttributeMaxDynamicSharedMemorySize, DYN_SMEM);

    // 1. convert X to fp16; repack weights as fp16 hi/lo (x256)
    conv_x_kernel<<<(B_SZ * KDIM / 4 + 255) / 256, 256>>>(X, xh);
    repack_w_kernel<<<(KDIM * KDIM + 255) / 256, 256>>>(Wi, whi, wlo, bias_p, t_p, u_p);
    repack_l_kernel<<<(KDIM * KDIM + 255) / 256, 256>>>(Wl, lhi, llo);

    // 2. GEMM1 + bias + sigmoid -> g_s (fp32, ld=1024)
    {
        dim3 grid(8, B_SZ / 128);   // (8, 128)
        mma_gemm_kernel<true><<<grid, 256, DYN_SMEM>>>(
            xh, whi, wlo, bias_p, s_p, 1024, 1024);
    }

    // 3. path probs (fp16) + regularizer partial sums
    path_kernel<<<B_SZ / SAMPLES_PER_BLOCK, 256>>>(s_p, php, t_p, u_p);

    // 4. GEMM2: predictions = path @ W_leaf^T -> d_out (ld=1000, clip 1000)
    {
        dim3 grid(8, B_SZ / 128);
        mma_gemm_kernel<false><<<grid, 256, DYN_SMEM>>>(
            php, lhi, llo, nullptr, out, OUT_DIM, OUT_DIM);
    }

    // 5. regularizer scalar -> last output element
    reg_kernel<<<1, 256>>>(t_p, u_p, out + (out_size - 1));
}

// round 11
// speedup vs baseline: 1.6416x; 1.2378x over previous
#include <cuda_runtime.h>
#include <cuda_fp16.h>
#include <cstdint>
#include <math.h>

// ---------------- problem constants ----------------
#define B_SZ      16384
#define KDIM      1024
#define OUT_DIM   1000
#define N_INT     1023
#define DEPTH     10
#define LAMBDA    1e-3f

// ---------------- scratch (device globals) ----------------
__device__ __half g_Xh[(size_t)B_SZ * KDIM];        // X as fp16
__device__ __half g_Ph[(size_t)B_SZ * KDIM];        // path probs fp16
__device__ __half g_Wh[(size_t)KDIM * KDIM];        // W_internal fp16
__device__ __half g_Lh[(size_t)KDIM * KDIM];        // W_leaf fp16
__device__ float g_s[(size_t)B_SZ * KDIM];
__device__ float g_bias[KDIM];
__device__ float g_T[1023];
__device__ float g_U[2046];

// ---------------- PTX helpers (sm_80-class features only) ----------------
__device__ __forceinline__ uint32_t smem_u32(const void* p) {
    uint32_t a;
    asm("{ .reg .u64 t; cvta.to.shared.u64 t, %1; cvt.u32.u64 %0, t; }" : "=r"(a) : "l"(p));
    return a;
}

#define CP_ASYNC16(dst, src) \
    asm volatile("cp.async.cg.shared.global [%0], [%1], 16;" :: "r"(dst), "l"(src))
#define CP_COMMIT() asm volatile("cp.async.commit_group;" ::: "memory")
#define CP_WAIT(n)  asm volatile("cp.async.wait_group %0;" :: "n"(n) : "memory")

#define LDMX4(r0, r1, r2, r3, addr) \
    asm volatile("ldmatrix.sync.aligned.m8n8.x4.shared.b16 {%0,%1,%2,%3}, [%4];" \
        : "=r"(r0), "=r"(r1), "=r"(r2), "=r"(r3) : "r"(addr))

#define MMAF16(d, a, b) \
    asm volatile("mma.sync.aligned.m16n8k16.row.col.f32.f16.f16.f32 " \
        "{%0,%1,%2,%3}, {%4,%5,%6,%7}, {%8,%9}, {%0,%1,%2,%3};" \
        : "+f"((d)[0]), "+f"((d)[1]), "+f"((d)[2]), "+f"((d)[3]) \
        : "r"((a)[0]), "r"((a)[1]), "r"((a)[2]), "r"((a)[3]), \
          "r"((b)[0]), "r"((b)[1]))

// X: fp32 -> fp16
__global__ void conv_x_kernel(const float* __restrict__ src,
                              __half* __restrict__ dst) {
    size_t i = (size_t)blockIdx.x * blockDim.x + threadIdx.x;  // quad index
    float4 v = ((const float4*)src)[i];
    ((__half2*)dst)[2 * i]     = __floats2half2_rn(v.x, v.y);
    ((__half2*)dst)[2 * i + 1] = __floats2half2_rn(v.z, v.w);
}

// W_internal: repack [1023,1025] -> aligned fp16 + fp32 bias; zero T/U
__global__ void repack_w_kernel(const float* __restrict__ Wi,
                                __half* __restrict__ wh,
                                float* __restrict__ bias,
                                float* __restrict__ t, float* __restrict__ u) {
    int idx = blockIdx.x * blockDim.x + threadIdx.x;
    if (idx < KDIM * KDIM) {
        int n = idx >> 10, k = idx & 1023;
        float v = (n < N_INT) ? Wi[(size_t)n * 1025 + 1 + k] : 0.0f;
        wh[idx] = __float2half_rn(v);
    }
    if (idx < KDIM) bias[idx] = (idx < N_INT) ? Wi[(size_t)idx * 1025] : 0.0f;
    if (idx < 1023) t[idx] = 0.0f;
    if (idx < 2046) u[idx] = 0.0f;
}

__global__ void repack_l_kernel(const float* __restrict__ Wl,
                                __half* __restrict__ lh) {
    int idx = blockIdx.x * blockDim.x + threadIdx.x;
    if (idx < KDIM * KDIM) {
        int n = idx >> 10, k = idx & 1023;
        float v = (n < OUT_DIM) ? Wl[(size_t)n * KDIM + k] : 0.0f;
        lh[idx] = __float2half_rn(v);
    }
}

// ---------------- mma.sync GEMM: C[M,N] = A * B^T, pure fp16 ---------------
// CTA tile 128x128, BK=32, 2-stage cp.async ring, 256 threads (8 warps 4Mx2N,
// warp tile 32x64), 2 CTAs/SM. One __syncthreads per BK=32 chunk.
#define ROWB        80                    // 64B data + 16B pad (conflict-free)
#define TROWS       128
#define OFF_A       0
#define OFF_B       (TROWS * ROWB)        // 10240
#define STAGE_BYTES (2 * TROWS * ROWB)    // 20480
#define NSTAGE      2
#define NCHUNK      32                    // K=1024 / BK=32
#define DYN_SMEM    (NSTAGE * STAGE_BYTES + 512)

__device__ __forceinline__ void load_stage(
        const __half* __restrict__ A, const __half* __restrict__ B,
        int m0, int n0, int chunk, uint32_t sb, int tid) {
    const int r = tid >> 2;            // 0..63
    const int c = tid & 3;             // 16B quarter of the 64B row
    const int kk = chunk * 32 + c * 8; // fp16 element offset
    const uint32_t doff = (uint32_t)r * ROWB + (uint32_t)c * 16;
#pragma unroll
    for (int h = 0; h < 2; h++) {
        const int rr = r + h * 64;
        const uint32_t d = sb + doff + (uint32_t)(h * 64 * ROWB);
        CP_ASYNC16(d + OFF_A, A + (size_t)(m0 + rr) * KDIM + kk);
        CP_ASYNC16(d + OFF_B, B + (size_t)(n0 + rr) * KDIM + kk);
    }
}

template<bool SIG>
__global__ void __launch_bounds__(256, 2)
mma_gemm_kernel(const __half* __restrict__ A, const __half* __restrict__ B,
                const float* __restrict__ bias, float* __restrict__ C,
                int ldc, int nclip) {
    extern __shared__ char sm[];
    const uint32_t s0 = smem_u32(sm);
    float* bias_sh = (float*)(sm + NSTAGE * STAGE_BYTES);

    const int tid  = threadIdx.x;
    const int lane = tid & 31;
    const int wid  = tid >> 5;
    const int wm   = wid & 3;    // 4 M-warps of 32 rows
    const int wn   = wid >> 2;   // 2 N-warps of 64 cols
    const int m0   = blockIdx.y * 128;
    const int n0   = blockIdx.x * 128;

    if (SIG && tid < 128) bias_sh[tid] = bias[n0 + tid];

    float acc[2][8][4];
#pragma unroll
    for (int mi = 0; mi < 2; mi++)
#pragma unroll
        for (int ni = 0; ni < 8; ni++)
#pragma unroll
            for (int j = 0; j < 4; j++) acc[mi][ni][j] = 0.0f;

    // ldmatrix per-thread address components
    const uint32_t a_off = (uint32_t)(wm * 32 + (lane & 15)) * ROWB
                         + (uint32_t)(lane >> 4) * 16;
    const uint32_t b_off = (uint32_t)(wn * 64 + ((lane >> 4) & 1) * 8 + (lane & 7)) * ROWB
                         + (uint32_t)((lane >> 3) & 1) * 16;

    // prologue: stage 0
    load_stage(A, B, m0, n0, 0, s0, tid);
    CP_COMMIT();

    for (int s = 0; s < NCHUNK; s++) {
        CP_WAIT(0);          // stage s landed (this thread)
        __syncthreads();     // stage s visible CTA-wide; stage s-1 reads all done

        const uint32_t sb = s0 + (uint32_t)(s & 1) * STAGE_BYTES;

#pragma unroll
        for (int ks = 0; ks < 2; ks++) {
            uint32_t ar[2][4];
#pragma unroll
            for (int mi = 0; mi < 2; mi++) {
                const uint32_t ao = sb + a_off + (uint32_t)(mi * 16 * ROWB)
                                  + (uint32_t)(ks * 32);
                LDMX4(ar[mi][0], ar[mi][1], ar[mi][2], ar[mi][3], ao + OFF_A);
            }
#pragma unroll
            for (int half = 0; half < 2; half++) {
                uint32_t br[4][2];
#pragma unroll
                for (int p = 0; p < 2; p++) {
                    const int pj = half * 2 + p;
                    const uint32_t bo = sb + b_off + (uint32_t)(pj * 16 * ROWB)
                                      + (uint32_t)(ks * 32);
                    LDMX4(br[2 * p][0], br[2 * p][1], br[2 * p + 1][0], br[2 * p + 1][1],
                          bo + OFF_B);
                }
#pragma unroll
                for (int mi = 0; mi < 2; mi++)
#pragma unroll
                    for (int nj = 0; nj < 4; nj++)
                        MMAF16(acc[mi][half * 4 + nj], ar[mi], br[nj]);
            }
            // prefetch next stage between k-steps
            if (ks == 0 && s + 1 < NCHUNK) {
                load_stage(A, B, m0, n0, s + 1,
                           s0 + (uint32_t)((s + 1) & 1) * STAGE_BYTES, tid);
                CP_COMMIT();
            }
        }
    }

    // epilogue: bias+sigmoid if SIG, direct float2 stores
    const int tr = lane >> 2;
    const int tc = (lane & 3) * 2;
#pragma unroll
    for (int mi = 0; mi < 2; mi++) {
#pragma unroll
        for (int ni = 0; ni < 8; ni++) {
            const int row = m0 + wm * 32 + mi * 16 + tr;
            const int col = n0 + wn * 64 + ni * 8 + tc;
            float v0 = acc[mi][ni][0], v1 = acc[mi][ni][1];
            float v2 = acc[mi][ni][2], v3 = acc[mi][ni][3];
            if (SIG) {
                const float b0 = bias_sh[col - n0];
                const float b1 = bias_sh[col - n0 + 1];
                v0 = 1.0f / (1.0f + expf(-(v0 + b0)));
                v1 = 1.0f / (1.0f + expf(-(v1 + b1)));
                v2 = 1.0f / (1.0f + expf(-(v2 + b0)));
                v3 = 1.0f / (1.0f + expf(-(v3 + b1)));
            }
            if (col < nclip) {  // col even, nclip even -> pair never straddles
                *(float2*)&C[(size_t)row * ldc + col]       = make_float2(v0, v1);
                *(float2*)&C[(size_t)(row + 8) * ldc + col] = make_float2(v2, v3);
            }
        }
    }
}

// ---------------- path + regularizer partial sums ----------------
#define SAMPLES_PER_BLOCK 8

__global__ void __launch_bounds__(256)
path_kernel(const float* __restrict__ s_g,
            __half* __restrict__ ph,
            float* __restrict__ gT, float* __restrict__ gU) {
    __shared__ float s_sh[1024];
    __shared__ float bufA[1024];
    __shared__ float bufB[1024];
    __shared__ float Tacc[1023];
    __shared__ float Uacc[2046];

    const int tid = threadIdx.x;
    for (int i = tid; i < 1023; i += 256) Tacc[i] = 0.0f;
    for (int i = tid; i < 2046; i += 256) Uacc[i] = 0.0f;

    const int base = blockIdx.x * SAMPLES_PER_BLOCK;

    for (int s = 0; s < SAMPLES_PER_BLOCK; s++) {
        const int b = base + s;
        __syncthreads();
        for (int i = tid; i < 1024; i += 256)
            s_sh[i] = s_g[(size_t)b * 1024 + i];
        if (tid == 0) bufA[0] = 1.0f;
        __syncthreads();

        float* cur = bufA;
        float* nxt = bufB;
        int toff = 0, uoff = 0;

#pragma unroll
        for (int d = 0; d < DEPTH; d++) {
            const int nout = 2 << d;
            const int nbase = (1 << d) - 1;
            for (int k = tid; k < nout; k += 256) {
                float sv = s_sh[nbase + (k >> 1)];
                float lp = (k & 1) ? (1.0f - sv) : sv;
                float nk = cur[k >> 1] * lp;
                nxt[k] = nk;
                int p = k >> 1;
                float svp = s_sh[nbase + (p >> 1)];
                float lpp = (p & 1) ? (1.0f - svp) : svp;
                float pn = cur[p >> 1] * lpp;
                Uacc[uoff + k] += lp * pn;
                if (k < (nout >> 1)) Tacc[toff + k] += nk;
            }
            __syncthreads();
            toff += nout >> 1;
            uoff += nout;
            float* t = cur; cur = nxt; nxt = t;
        }

        for (int l = tid; l < 1024; l += 256)
            ph[(size_t)b * 1024 + l] = __float2half_rn(cur[l]);
    }

    __syncthreads();
    for (int i = tid; i < 1023; i += 256) atomicAdd(&gT[i], Tacc[i]);
    for (int i = tid; i < 2046; i += 256) atomicAdd(&gU[i], Uacc[i]);
}

// ---------------- regularizer scalar ----------------
__global__ void reg_kernel(const float* __restrict__ gT, const float* __restrict__ gU,
                           float* __restrict__ out) {
    float local = 0.0f;
    int toff = 0, uoff = 0;
#pragma unroll
    for (int d = 0; d < DEPTH; d++) {
        const int nout = 2 << d;
        const float factor = LAMBDA * exp2f(-(float)d);
        for (int k = threadIdx.x; k < nout; k += 256) {
            float den = gT[toff + (k >> 1)] + 1e-8f;
            float alpha = gU[uoff + k] / den;
            local += factor * (-0.5f) * (logf(alpha) + logf(1.0f - alpha));
        }
        toff += (1 << d);
        uoff += nout;
    }
    __shared__ float red[256];
    red[threadIdx.x] = local;
    __syncthreads();
    for (int s = 128; s > 0; s >>= 1) {
        if (threadIdx.x < s) red[threadIdx.x] += red[threadIdx.x + s];
        __syncthreads();
    }
    if (threadIdx.x == 0) out[0] = red[0];
}

// ---------------- launch ----------------
extern "C" void kernel_launch(void* const* d_in, const int* in_sizes, int n_in,
                              void* d_out, int out_size) {
    const float* X  = (const float*)d_in[0];   // [16384, 1024]
    const float* Wi = (const float*)d_in[1];   // [1023, 1025]
    const float* Wl = (const float*)d_in[2];   // [1000, 1024]
    float* out = (float*)d_out;

    __half *xh, *php, *wh, *lh;
    float *s_p, *bias_p, *t_p, *u_p;
    cudaGetSymbolAddress((void**)&xh,   g_Xh);
    cudaGetSymbolAddress((void**)&php,  g_Ph);
    cudaGetSymbolAddress((void**)&wh,   g_Wh);
    cudaGetSymbolAddress((void**)&lh,   g_Lh);
    cudaGetSymbolAddress((void**)&s_p,  g_s);
    cudaGetSymbolAddress((void**)&bias_p, g_bias);
    cudaGetSymbolAddress((void**)&t_p,  g_T);
    cudaGetSymbolAddress((void**)&u_p,  g_U);

    cudaFuncSetAttribute(mma_gemm_kernel<true>,
                         cudaFuncAttributeMaxDynamicSharedMemorySize, DYN_SMEM);
    cudaFuncSetAttribute(mma_gemm_kernel<false>,
                         cudaFuncAttributeMaxDynamicSharedMemorySize, DYN_SMEM);

    // 1. convert X and weights to fp16
    conv_x_kernel<<<(B_SZ * KDIM / 4 + 255) / 256, 256>>>(X, xh);
    repack_w_kernel<<<(KDIM * KDIM + 255) / 256, 256>>>(Wi, wh, bias_p, t_p, u_p);
    repack_l_kernel<<<(KDIM * KDIM + 255) / 256, 256>>>(Wl, lh);

    // 2. GEMM1 + bias + sigmoid -> g_s (fp32, ld=1024)
    {
        dim3 grid(8, B_SZ / 128);   // (8, 128)
        mma_gemm_kernel<true><<<grid, 256, DYN_SMEM>>>(
            xh, wh, bias_p, s_p, 1024, 1024);
    }

    // 3. path probs (fp16) + regularizer partial sums
    path_kernel<<<B_SZ / SAMPLES_PER_BLOCK, 256>>>(s_p, php, t_p, u_p);

    // 4. GEMM2: predictions = path @ W_leaf^T -> d_out (ld=1000, clip 1000)
    {
        dim3 grid(8, B_SZ / 128);
        mma_gemm_kernel<false><<<grid, 256, DYN_SMEM>>>(
            php, lh, nullptr, out, OUT_DIM, OUT_DIM);
    }

    // 5. regularizer scalar -> last output element
    reg_kernel<<<1, 256>>>(t_p, u_p, out + (out_size - 1));
}

// round 12
// speedup vs baseline: 1.7966x; 1.0944x over previous
#include <cuda_runtime.h>
#include <cuda_fp16.h>
#include <cstdint>
#include <math.h>

// ---------------- problem constants ----------------
#define B_SZ      16384
#define KDIM      1024
#define OUT_DIM   1000
#define N_INT     1023
#define DEPTH     10
#define LAMBDA    1e-3f

// ---------------- scratch (device globals) ----------------
__device__ __half g_Xh[(size_t)B_SZ * KDIM];        // X as fp16
__device__ __half g_Ph[(size_t)B_SZ * KDIM];        // path probs fp16
__device__ __half g_Wh[(size_t)KDIM * KDIM];        // W_internal fp16
__device__ __half g_Lh[(size_t)KDIM * KDIM];        // W_leaf fp16
__device__ float g_s[(size_t)B_SZ * KDIM];
__device__ float g_bias[KDIM];
__device__ float g_T[1023];
__device__ float g_U[2046];

// ---------------- PTX helpers (sm_80-class features only) ----------------
__device__ __forceinline__ uint32_t smem_u32(const void* p) {
    uint32_t a;
    asm("{ .reg .u64 t; cvta.to.shared.u64 t, %1; cvt.u32.u64 %0, t; }" : "=r"(a) : "l"(p));
    return a;
}

#define CP_ASYNC16(dst, src) \
    asm volatile("cp.async.cg.shared.global [%0], [%1], 16;" :: "r"(dst), "l"(src))
#define CP_COMMIT() asm volatile("cp.async.commit_group;" ::: "memory")
#define CP_WAIT(n)  asm volatile("cp.async.wait_group %0;" :: "n"(n) : "memory")

#define LDMX4(r0, r1, r2, r3, addr) \
    asm volatile("ldmatrix.sync.aligned.m8n8.x4.shared.b16 {%0,%1,%2,%3}, [%4];" \
        : "=r"(r0), "=r"(r1), "=r"(r2), "=r"(r3) : "r"(addr))

#define MMAF16(d, a, b) \
    asm volatile("mma.sync.aligned.m16n8k16.row.col.f32.f16.f16.f32 " \
        "{%0,%1,%2,%3}, {%4,%5,%6,%7}, {%8,%9}, {%0,%1,%2,%3};" \
        : "+f"((d)[0]), "+f"((d)[1]), "+f"((d)[2]), "+f"((d)[3]) \
        : "r"((a)[0]), "r"((a)[1]), "r"((a)[2]), "r"((a)[3]), \
          "r"((b)[0]), "r"((b)[1]))

// X: fp32 -> fp16
__global__ void conv_x_kernel(const float* __restrict__ src,
                              __half* __restrict__ dst) {
    size_t i = (size_t)blockIdx.x * blockDim.x + threadIdx.x;  // quad index
    float4 v = ((const float4*)src)[i];
    ((__half2*)dst)[2 * i]     = __floats2half2_rn(v.x, v.y);
    ((__half2*)dst)[2 * i + 1] = __floats2half2_rn(v.z, v.w);
}

// W_internal: repack [1023,1025] -> aligned fp16 + fp32 bias; zero T/U
__global__ void repack_w_kernel(const float* __restrict__ Wi,
                                __half* __restrict__ wh,
                                float* __restrict__ bias,
                                float* __restrict__ t, float* __restrict__ u) {
    int idx = blockIdx.x * blockDim.x + threadIdx.x;
    if (idx < KDIM * KDIM) {
        int n = idx >> 10, k = idx & 1023;
        float v = (n < N_INT) ? Wi[(size_t)n * 1025 + 1 + k] : 0.0f;
        wh[idx] = __float2half_rn(v);
    }
    if (idx < KDIM) bias[idx] = (idx < N_INT) ? Wi[(size_t)idx * 1025] : 0.0f;
    if (idx < 1023) t[idx] = 0.0f;
    if (idx < 2046) u[idx] = 0.0f;
}

__global__ void repack_l_kernel(const float* __restrict__ Wl,
                                __half* __restrict__ lh) {
    int idx = blockIdx.x * blockDim.x + threadIdx.x;
    if (idx < KDIM * KDIM) {
        int n = idx >> 10, k = idx & 1023;
        float v = (n < OUT_DIM) ? Wl[(size_t)n * KDIM + k] : 0.0f;
        lh[idx] = __float2half_rn(v);
    }
}

// ---------------- mma.sync GEMM: C[M,N] = A * B^T, pure fp16 ---------------
// CTA tile 128x128, BK=64, 2-stage cp.async ring, 256 threads (8 warps 4Mx2N,
// warp tile 32x64), 2 CTAs/SM. One __syncthreads per BK=64 chunk; prefetch
// issued immediately after the barrier (full-chunk latency shadow).
#define ROWB        144                   // 128B data + 16B pad (conflict-free)
#define TROWS       128
#define OFF_A       0
#define OFF_B       (TROWS * ROWB)        // 18432
#define STAGE_BYTES (2 * TROWS * ROWB)    // 36864
#define NSTAGE      2
#define NCHUNK      16                    // K=1024 / BK=64
#define DYN_SMEM    (NSTAGE * STAGE_BYTES + 512)

__device__ __forceinline__ void load_stage(
        const __half* __restrict__ A, const __half* __restrict__ B,
        int m0, int n0, int chunk, uint32_t sb, int tid) {
    const int r = tid >> 3;            // 0..31
    const int c = tid & 7;             // 16B eighth of the 128B row
    const int kk = chunk * 64 + c * 8; // fp16 element offset
    const uint32_t doff = (uint32_t)r * ROWB + (uint32_t)c * 16;
#pragma unroll
    for (int h = 0; h < 4; h++) {
        const int rr = r + h * 32;
        const uint32_t d = sb + doff + (uint32_t)(h * 32 * ROWB);
        CP_ASYNC16(d + OFF_A, A + (size_t)(m0 + rr) * KDIM + kk);
        CP_ASYNC16(d + OFF_B, B + (size_t)(n0 + rr) * KDIM + kk);
    }
}

template<bool SIG>
__global__ void __launch_bounds__(256, 2)
mma_gemm_kernel(const __half* __restrict__ A, const __half* __restrict__ B,
                const float* __restrict__ bias, float* __restrict__ C,
                int ldc, int nclip) {
    extern __shared__ char sm[];
    const uint32_t s0 = smem_u32(sm);
    float* bias_sh = (float*)(sm + NSTAGE * STAGE_BYTES);

    const int tid  = threadIdx.x;
    const int lane = tid & 31;
    const int wid  = tid >> 5;
    const int wm   = wid & 3;    // 4 M-warps of 32 rows
    const int wn   = wid >> 2;   // 2 N-warps of 64 cols
    const int m0   = blockIdx.y * 128;
    const int n0   = blockIdx.x * 128;

    if (SIG && tid < 128) bias_sh[tid] = bias[n0 + tid];

    float acc[2][8][4];
#pragma unroll
    for (int mi = 0; mi < 2; mi++)
#pragma unroll
        for (int ni = 0; ni < 8; ni++)
#pragma unroll
            for (int j = 0; j < 4; j++) acc[mi][ni][j] = 0.0f;

    // ldmatrix per-thread address components (within a 128B row)
    const uint32_t a_off = (uint32_t)(wm * 32 + (lane & 15)) * ROWB
                         + (uint32_t)(lane >> 4) * 16;
    const uint32_t b_off = (uint32_t)(wn * 64 + ((lane >> 4) & 1) * 8 + (lane & 7)) * ROWB
                         + (uint32_t)((lane >> 3) & 1) * 16;

    // prologue: stage 0
    load_stage(A, B, m0, n0, 0, s0, tid);
    CP_COMMIT();

    for (int s = 0; s < NCHUNK; s++) {
        CP_WAIT(0);          // stage s landed (this thread)
        __syncthreads();     // stage s visible CTA-wide; stage s-1 reads all done

        // prefetch stage s+1 NOW: its buffer was consumed in chunk s-1, so it
        // is free; gives a full chunk of latency shadow.
        if (s + 1 < NCHUNK) {
            load_stage(A, B, m0, n0, s + 1,
                       s0 + (uint32_t)((s + 1) & 1) * STAGE_BYTES, tid);
            CP_COMMIT();
        }

        const uint32_t sb = s0 + (uint32_t)(s & 1) * STAGE_BYTES;

#pragma unroll
        for (int ks = 0; ks < 4; ks++) {
            uint32_t ar[2][4];
#pragma unroll
            for (int mi = 0; mi < 2; mi++) {
                const uint32_t ao = sb + a_off + (uint32_t)(mi * 16 * ROWB)
                                  + (uint32_t)(ks * 32);
                LDMX4(ar[mi][0], ar[mi][1], ar[mi][2], ar[mi][3], ao + OFF_A);
            }
#pragma unroll
            for (int half = 0; half < 2; half++) {
                uint32_t br[4][2];
#pragma unroll
                for (int p = 0; p < 2; p++) {
                    const int pj = half * 2 + p;
                    const uint32_t bo = sb + b_off + (uint32_t)(pj * 16 * ROWB)
                                      + (uint32_t)(ks * 32);
                    LDMX4(br[2 * p][0], br[2 * p][1], br[2 * p + 1][0], br[2 * p + 1][1],
                          bo + OFF_B);
                }
#pragma unroll
                for (int mi = 0; mi < 2; mi++)
#pragma unroll
                    for (int nj = 0; nj < 4; nj++)
                        MMAF16(acc[mi][half * 4 + nj], ar[mi], br[nj]);
            }
        }
    }

    // epilogue: bias+sigmoid if SIG, direct float2 stores
    const int tr = lane >> 2;
    const int tc = (lane & 3) * 2;
#pragma unroll
    for (int mi = 0; mi < 2; mi++) {
#pragma unroll
        for (int ni = 0; ni < 8; ni++) {
            const int row = m0 + wm * 32 + mi * 16 + tr;
            const int col = n0 + wn * 64 + ni * 8 + tc;
            float v0 = acc[mi][ni][0], v1 = acc[mi][ni][1];
            float v2 = acc[mi][ni][2], v3 = acc[mi][ni][3];
            if (SIG) {
                const float b0 = bias_sh[col - n0];
                const float b1 = bias_sh[col - n0 + 1];
                v0 = 1.0f / (1.0f + expf(-(v0 + b0)));
                v1 = 1.0f / (1.0f + expf(-(v1 + b1)));
                v2 = 1.0f / (1.0f + expf(-(v2 + b0)));
                v3 = 1.0f / (1.0f + expf(-(v3 + b1)));
            }
            if (col < nclip) {  // col even, nclip even -> pair never straddles
                *(float2*)&C[(size_t)row * ldc + col]       = make_float2(v0, v1);
                *(float2*)&C[(size_t)(row + 8) * ldc + col] = make_float2(v2, v3);
            }
        }
    }
}

// ---------------- path + regularizer partial sums ----------------
#define SAMPLES_PER_BLOCK 8

__global__ void __launch_bounds__(256)
path_kernel(const float* __restrict__ s_g,
            __half* __restrict__ ph,
            float* __restrict__ gT, float* __restrict__ gU) {
    __shared__ float s_sh[1024];
    __shared__ float bufA[1024];
    __shared__ float bufB[1024];
    __shared__ float Tacc[1023];
    __shared__ float Uacc[2046];

    const int tid = threadIdx.x;
    for (int i = tid; i < 1023; i += 256) Tacc[i] = 0.0f;
    for (int i = tid; i < 2046; i += 256) Uacc[i] = 0.0f;

    const int base = blockIdx.x * SAMPLES_PER_BLOCK;

    for (int s = 0; s < SAMPLES_PER_BLOCK; s++) {
        const int b = base + s;
        __syncthreads();
        for (int i = tid; i < 1024; i += 256)
            s_sh[i] = s_g[(size_t)b * 1024 + i];
        if (tid == 0) bufA[0] = 1.0f;
        __syncthreads();

        float* cur = bufA;
        float* nxt = bufB;
        int toff = 0, uoff = 0;

#pragma unroll
        for (int d = 0; d < DEPTH; d++) {
            const int nout = 2 << d;
            const int nbase = (1 << d) - 1;
            for (int k = tid; k < nout; k += 256) {
                float sv = s_sh[nbase + (k >> 1)];
                float lp = (k & 1) ? (1.0f - sv) : sv;
                float nk = cur[k >> 1] * lp;
                nxt[k] = nk;
                int p = k >> 1;
                float svp = s_sh[nbase + (p >> 1)];
                float lpp = (p & 1) ? (1.0f - svp) : svp;
                float pn = cur[p >> 1] * lpp;
                Uacc[uoff + k] += lp * pn;
                if (k < (nout >> 1)) Tacc[toff + k] += nk;
            }
            __syncthreads();
            toff += nout >> 1;
            uoff += nout;
            float* t = cur; cur = nxt; nxt = t;
        }

        for (int l = tid; l < 1024; l += 256)
            ph[(size_t)b * 1024 + l] = __float2half_rn(cur[l]);
    }

    __syncthreads();
    for (int i = tid; i < 1023; i += 256) atomicAdd(&gT[i], Tacc[i]);
    for (int i = tid; i < 2046; i += 256) atomicAdd(&gU[i], Uacc[i]);
}

// ---------------- regularizer scalar ----------------
__global__ void reg_kernel(const float* __restrict__ gT, const float* __restrict__ gU,
                           float* __restrict__ out) {
    float local = 0.0f;
    int toff = 0, uoff = 0;
#pragma unroll
    for (int d = 0; d < DEPTH; d++) {
        const int nout = 2 << d;
        const float factor = LAMBDA * exp2f(-(float)d);
        for (int k = threadIdx.x; k < nout; k += 256) {
            float den = gT[toff + (k >> 1)] + 1e-8f;
            float alpha = gU[uoff + k] / den;
            local += factor * (-0.5f) * (logf(alpha) + logf(1.0f - alpha));
        }
        toff += (1 << d);
        uoff += nout;
    }
    __shared__ float red[256];
    red[threadIdx.x] = local;
    __syncthreads();
    for (int s = 128; s > 0; s >>= 1) {
        if (threadIdx.x < s) red[threadIdx.x] += red[threadIdx.x + s];
        __syncthreads();
    }
    if (threadIdx.x == 0) out[0] = red[0];
}

// ---------------- launch ----------------
extern "C" void kernel_launch(void* const* d_in, const int* in_sizes, int n_in,
                              void* d_out, int out_size) {
    const float* X  = (const float*)d_in[0];   // [16384, 1024]
    const float* Wi = (const float*)d_in[1];   // [1023, 1025]
    const float* Wl = (const float*)d_in[2];   // [1000, 1024]
    float* out = (float*)d_out;

    __half *xh, *php, *wh, *lh;
    float *s_p, *bias_p, *t_p, *u_p;
    cudaGetSymbolAddress((void**)&xh,   g_Xh);
    cudaGetSymbolAddress((void**)&php,  g_Ph);
    cudaGetSymbolAddress((void**)&wh,   g_Wh);
    cudaGetSymbolAddress((void**)&lh,   g_Lh);
    cudaGetSymbolAddress((void**)&s_p,  g_s);
    cudaGetSymbolAddress((void**)&bias_p, g_bias);
    cudaGetSymbolAddress((void**)&t_p,  g_T);
    cudaGetSymbolAddress((void**)&u_p,  g_U);

    cudaFuncSetAttribute(mma_gemm_kernel<true>,
                         cudaFuncAttributeMaxDynamicSharedMemorySize, DYN_SMEM);
    cudaFuncSetAttribute(mma_gemm_kernel<false>,
                         cudaFuncAttributeMaxDynamicSharedMemorySize, DYN_SMEM);

    // 1. convert X and weights to fp16
    conv_x_kernel<<<(B_SZ * KDIM / 4 + 255) / 256, 256>>>(X, xh);
    repack_w_kernel<<<(KDIM * KDIM + 255) / 256, 256>>>(Wi, wh, bias_p, t_p, u_p);
    repack_l_kernel<<<(KDIM * KDIM + 255) / 256, 256>>>(Wl, lh);

    // 2. GEMM1 + bias + sigmoid -> g_s (fp32, ld=1024)
    {
        dim3 grid(8, B_SZ / 128);   // (8, 128)
        mma_gemm_kernel<true><<<grid, 256, DYN_SMEM>>>(
            xh, wh, bias_p, s_p, 1024, 1024);
    }

    // 3. path probs (fp16) + regularizer partial sums
    path_kernel<<<B_SZ / SAMPLES_PER_BLOCK, 256>>>(s_p, php, t_p, u_p);

    // 4. GEMM2: predictions = path @ W_leaf^T -> d_out (ld=1000, clip 1000)
    {
        dim3 grid(8, B_SZ / 128);
        mma_gemm_kernel<false><<<grid, 256, DYN_SMEM>>>(
            php, lh, nullptr, out, OUT_DIM, OUT_DIM);
    }

    // 5. regularizer scalar -> last output element
    reg_kernel<<<1, 256>>>(t_p, u_p, out + (out_size - 1));
}

// round 13
// speedup vs baseline: 1.8704x; 1.0411x over previous
#include <cuda_runtime.h>
#include <cuda_fp16.h>
#include <cstdint>
#include <math.h>

// ---------------- problem constants ----------------
#define B_SZ      16384
#define KDIM      1024
#define OUT_DIM   1000
#define N_INT     1023
#define DEPTH     10
#define LAMBDA    1e-3f

// ---------------- scratch (device globals) ----------------
__device__ __half g_Xh[(size_t)B_SZ * KDIM];        // X as fp16
__device__ __half g_Ph[(size_t)B_SZ * KDIM];        // path probs fp16
__device__ __half g_Wh[(size_t)KDIM * KDIM];        // W_internal fp16
__device__ __half g_Lh[(size_t)KDIM * KDIM];        // W_leaf fp16
__device__ __half g_s[(size_t)B_SZ * KDIM];         // sigmoid-0.5, fp16 (centered)
__device__ float g_bias[KDIM];
__device__ float g_T[1023];
__device__ float g_U[2046];

// ---------------- PTX helpers (sm_80-class features only) ----------------
__device__ __forceinline__ uint32_t smem_u32(const void* p) {
    uint32_t a;
    asm("{ .reg .u64 t; cvta.to.shared.u64 t, %1; cvt.u32.u64 %0, t; }" : "=r"(a) : "l"(p));
    return a;
}

#define CP_ASYNC16(dst, src) \
    asm volatile("cp.async.cg.shared.global [%0], [%1], 16;" :: "r"(dst), "l"(src))
#define CP_COMMIT() asm volatile("cp.async.commit_group;" ::: "memory")
#define CP_WAIT(n)  asm volatile("cp.async.wait_group %0;" :: "n"(n) : "memory")

#define LDMX4(r0, r1, r2, r3, addr) \
    asm volatile("ldmatrix.sync.aligned.m8n8.x4.shared.b16 {%0,%1,%2,%3}, [%4];" \
        : "=r"(r0), "=r"(r1), "=r"(r2), "=r"(r3) : "r"(addr))

#define MMAF16(d, a, b) \
    asm volatile("mma.sync.aligned.m16n8k16.row.col.f32.f16.f16.f32 " \
        "{%0,%1,%2,%3}, {%4,%5,%6,%7}, {%8,%9}, {%0,%1,%2,%3};" \
        : "+f"((d)[0]), "+f"((d)[1]), "+f"((d)[2]), "+f"((d)[3]) \
        : "r"((a)[0]), "r"((a)[1]), "r"((a)[2]), "r"((a)[3]), \
          "r"((b)[0]), "r"((b)[1]))

// X: fp32 -> fp16
__global__ void conv_x_kernel(const float* __restrict__ src,
                              __half* __restrict__ dst) {
    size_t i = (size_t)blockIdx.x * blockDim.x + threadIdx.x;  // quad index
    float4 v = ((const float4*)src)[i];
    ((__half2*)dst)[2 * i]     = __floats2half2_rn(v.x, v.y);
    ((__half2*)dst)[2 * i + 1] = __floats2half2_rn(v.z, v.w);
}

// W_internal: repack [1023,1025] -> aligned fp16 + fp32 bias; zero T/U
__global__ void repack_w_kernel(const float* __restrict__ Wi,
                                __half* __restrict__ wh,
                                float* __restrict__ bias,
                                float* __restrict__ t, float* __restrict__ u) {
    int idx = blockIdx.x * blockDim.x + threadIdx.x;
    if (idx < KDIM * KDIM) {
        int n = idx >> 10, k = idx & 1023;
        float v = (n < N_INT) ? Wi[(size_t)n * 1025 + 1 + k] : 0.0f;
        wh[idx] = __float2half_rn(v);
    }
    if (idx < KDIM) bias[idx] = (idx < N_INT) ? Wi[(size_t)idx * 1025] : 0.0f;
    if (idx < 1023) t[idx] = 0.0f;
    if (idx < 2046) u[idx] = 0.0f;
}

__global__ void repack_l_kernel(const float* __restrict__ Wl,
                                __half* __restrict__ lh) {
    int idx = blockIdx.x * blockDim.x + threadIdx.x;
    if (idx < KDIM * KDIM) {
        int n = idx >> 10, k = idx & 1023;
        float v = (n < OUT_DIM) ? Wl[(size_t)n * KDIM + k] : 0.0f;
        lh[idx] = __float2half_rn(v);
    }
}

// ---------------- mma.sync GEMM: C[M,N] = A * B^T, pure fp16 ---------------
// CTA tile 128x128, BK=64, 3-stage cp.async ring, 256 threads (8 warps 4Mx2N,
// warp tile 32x64), 2 CTAs/SM. One __syncthreads per BK=64 chunk; 2-chunk
// prefetch shadow so CP_WAIT(1) at chunk top is usually already satisfied.
// SIG=true: epilogue sigmoid-0.5 -> fp16 (centered). SIG=false: fp32 out.
#define ROWB        144                   // 128B data + 16B pad (conflict-free)
#define TROWS       128
#define OFF_A       0
#define OFF_B       (TROWS * ROWB)        // 18432
#define STAGE_BYTES (2 * TROWS * ROWB)    // 36864
#define NSTAGE      3
#define NCHUNK      16                    // K=1024 / BK=64
#define DYN_SMEM    (NSTAGE * STAGE_BYTES + 512)

__device__ __forceinline__ void load_stage(
        const __half* __restrict__ A, const __half* __restrict__ B,
        int m0, int n0, int chunk, uint32_t sb, int tid) {
    const int r = tid >> 3;            // 0..31
    const int c = tid & 7;             // 16B eighth of the 128B row
    const int kk = chunk * 64 + c * 8; // fp16 element offset
    const uint32_t doff = (uint32_t)r * ROWB + (uint32_t)c * 16;
#pragma unroll
    for (int h = 0; h < 4; h++) {
        const int rr = r + h * 32;
        const uint32_t d = sb + doff + (uint32_t)(h * 32 * ROWB);
        CP_ASYNC16(d + OFF_A, A + (size_t)(m0 + rr) * KDIM + kk);
        CP_ASYNC16(d + OFF_B, B + (size_t)(n0 + rr) * KDIM + kk);
    }
}

template<bool SIG>
__global__ void __launch_bounds__(256, 2)
mma_gemm_kernel(const __half* __restrict__ A, const __half* __restrict__ B,
                const float* __restrict__ bias, void* __restrict__ Cv,
                int ldc, int nclip) {
    extern __shared__ char sm[];
    const uint32_t s0 = smem_u32(sm);
    float* bias_sh = (float*)(sm + NSTAGE * STAGE_BYTES);

    const int tid  = threadIdx.x;
    const int lane = tid & 31;
    const int wid  = tid >> 5;
    const int wm   = wid & 3;    // 4 M-warps of 32 rows
    const int wn   = wid >> 2;   // 2 N-warps of 64 cols
    const int m0   = blockIdx.y * 128;
    const int n0   = blockIdx.x * 128;

    if (SIG && tid < 128) bias_sh[tid] = bias[n0 + tid];

    float acc[2][8][4];
#pragma unroll
    for (int mi = 0; mi < 2; mi++)
#pragma unroll
        for (int ni = 0; ni < 8; ni++)
#pragma unroll
            for (int j = 0; j < 4; j++) acc[mi][ni][j] = 0.0f;

    // ldmatrix per-thread address components (within a 128B row)
    const uint32_t a_off = (uint32_t)(wm * 32 + (lane & 15)) * ROWB
                         + (uint32_t)(lane >> 4) * 16;
    const uint32_t b_off = (uint32_t)(wn * 64 + ((lane >> 4) & 1) * 8 + (lane & 7)) * ROWB
                         + (uint32_t)((lane >> 3) & 1) * 16;

    // prologue: stages 0,1
    load_stage(A, B, m0, n0, 0, s0, tid);               CP_COMMIT();
    load_stage(A, B, m0, n0, 1, s0 + STAGE_BYTES, tid); CP_COMMIT();

    for (int s = 0; s < NCHUNK; s++) {
        if (s + 1 < NCHUNK) CP_WAIT(1);   // stage s done; s+1 may be in flight
        else                CP_WAIT(0);
        __syncthreads();                  // stage s visible; stage s-1 consumed

        // prefetch stage s+2 into the slot freed at chunk s-1
        if (s + 2 < NCHUNK) {
            load_stage(A, B, m0, n0, s + 2,
                       s0 + (uint32_t)((s + 2) % 3) * STAGE_BYTES, tid);
            CP_COMMIT();
        }

        const uint32_t sb = s0 + (uint32_t)(s % 3) * STAGE_BYTES;

#pragma unroll
        for (int ks = 0; ks < 4; ks++) {
            uint32_t ar[2][4];
#pragma unroll
            for (int mi = 0; mi < 2; mi++) {
                const uint32_t ao = sb + a_off + (uint32_t)(mi * 16 * ROWB)
                                  + (uint32_t)(ks * 32);
                LDMX4(ar[mi][0], ar[mi][1], ar[mi][2], ar[mi][3], ao + OFF_A);
            }
#pragma unroll
            for (int half = 0; half < 2; half++) {
                uint32_t br[4][2];
#pragma unroll
                for (int p = 0; p < 2; p++) {
                    const int pj = half * 2 + p;
                    const uint32_t bo = sb + b_off + (uint32_t)(pj * 16 * ROWB)
                                      + (uint32_t)(ks * 32);
                    LDMX4(br[2 * p][0], br[2 * p][1], br[2 * p + 1][0], br[2 * p + 1][1],
                          bo + OFF_B);
                }
#pragma unroll
                for (int mi = 0; mi < 2; mi++)
#pragma unroll
                    for (int nj = 0; nj < 4; nj++)
                        MMAF16(acc[mi][half * 4 + nj], ar[mi], br[nj]);
            }
        }
    }

    // epilogue
    const int tr = lane >> 2;
    const int tc = (lane & 3) * 2;
#pragma unroll
    for (int mi = 0; mi < 2; mi++) {
#pragma unroll
        for (int ni = 0; ni < 8; ni++) {
            const int row = m0 + wm * 32 + mi * 16 + tr;
            const int col = n0 + wn * 64 + ni * 8 + tc;
            float v0 = acc[mi][ni][0], v1 = acc[mi][ni][1];
            float v2 = acc[mi][ni][2], v3 = acc[mi][ni][3];
            if (SIG) {
                // centered sigmoid: sigmoid(x) - 0.5, stored fp16
                const float b0 = bias_sh[col - n0];
                const float b1 = bias_sh[col - n0 + 1];
                v0 = 1.0f / (1.0f + expf(-(v0 + b0))) - 0.5f;
                v1 = 1.0f / (1.0f + expf(-(v1 + b1))) - 0.5f;
                v2 = 1.0f / (1.0f + expf(-(v2 + b0))) - 0.5f;
                v3 = 1.0f / (1.0f + expf(-(v3 + b1))) - 0.5f;
                __half* C = (__half*)Cv;
                *(__half2*)&C[(size_t)row * ldc + col]       = __floats2half2_rn(v0, v1);
                *(__half2*)&C[(size_t)(row + 8) * ldc + col] = __floats2half2_rn(v2, v3);
            } else {
                float* C = (float*)Cv;
                if (col < nclip) {  // col even, nclip even -> pair never straddles
                    *(float2*)&C[(size_t)row * ldc + col]       = make_float2(v0, v1);
                    *(float2*)&C[(size_t)(row + 8) * ldc + col] = make_float2(v2, v3);
                }
            }
        }
    }
}

// ---------------- path + regularizer partial sums ----------------
// g_s holds centered sigmoids c = s - 0.5 in fp16; lp = 0.5+c / 0.5-c.
#define SAMPLES_PER_BLOCK 8

__global__ void __launch_bounds__(256)
path_kernel(const __half* __restrict__ s_g,
            __half* __restrict__ ph,
            float* __restrict__ gT, float* __restrict__ gU) {
    __shared__ float s_sh[1024];   // reconstructed sigmoid values
    __shared__ float bufA[1024];
    __shared__ float bufB[1024];
    __shared__ float Tacc[1023];
    __shared__ float Uacc[2046];

    const int tid = threadIdx.x;
    for (int i = tid; i < 1023; i += 256) Tacc[i] = 0.0f;
    for (int i = tid; i < 2046; i += 256) Uacc[i] = 0.0f;

    const int base = blockIdx.x * SAMPLES_PER_BLOCK;

    for (int s = 0; s < SAMPLES_PER_BLOCK; s++) {
        const int b = base + s;
        __syncthreads();
        // load 512 half2 (centered), reconstruct s = 0.5 + c
        for (int i = tid; i < 512; i += 256) {
            __half2 cv = ((const __half2*)(s_g + (size_t)b * 1024))[i];
            float2 cf = __half22float2(cv);
            s_sh[2 * i]     = 0.5f + cf.x;
            s_sh[2 * i + 1] = 0.5f + cf.y;
        }
        if (tid == 0) bufA[0] = 1.0f;
        __syncthreads();

        float* cur = bufA;
        float* nxt = bufB;
        int toff = 0, uoff = 0;

#pragma unroll
        for (int d = 0; d < DEPTH; d++) {
            const int nout = 2 << d;
            const int nbase = (1 << d) - 1;
            for (int k = tid; k < nout; k += 256) {
                float sv = s_sh[nbase + (k >> 1)];
                float lp = (k & 1) ? (1.0f - sv) : sv;
                float nk = cur[k >> 1] * lp;
                nxt[k] = nk;
                int p = k >> 1;
                float svp = s_sh[nbase + (p >> 1)];
                float lpp = (p & 1) ? (1.0f - svp) : svp;
                float pn = cur[p >> 1] * lpp;
                Uacc[uoff + k] += lp * pn;
                if (k < (nout >> 1)) Tacc[toff + k] += nk;
            }
            __syncthreads();
            toff += nout >> 1;
            uoff += nout;
            float* t = cur; cur = nxt; nxt = t;
        }

        for (int l = tid; l < 1024; l += 256)
            ph[(size_t)b * 1024 + l] = __float2half_rn(cur[l]);
    }

    __syncthreads();
    for (int i = tid; i < 1023; i += 256) atomicAdd(&gT[i], Tacc[i]);
    for (int i = tid; i < 2046; i += 256) atomicAdd(&gU[i], Uacc[i]);
}

// ---------------- regularizer scalar ----------------
__global__ void reg_kernel(const float* __restrict__ gT, const float* __restrict__ gU,
                           float* __restrict__ out) {
    float local = 0.0f;
    int toff = 0, uoff = 0;
#pragma unroll
    for (int d = 0; d < DEPTH; d++) {
        const int nout = 2 << d;
        const float factor = LAMBDA * exp2f(-(float)d);
        for (int k = threadIdx.x; k < nout; k += 256) {
            float den = gT[toff + (k >> 1)] + 1e-8f;
            float alpha = gU[uoff + k] / den;
            local += factor * (-0.5f) * (logf(alpha) + logf(1.0f - alpha));
        }
        toff += (1 << d);
        uoff += nout;
    }
    __shared__ float red[256];
    red[threadIdx.x] = local;
    __syncthreads();
    for (int s = 128; s > 0; s >>= 1) {
        if (threadIdx.x < s) red[threadIdx.x] += red[threadIdx.x + s];
        __syncthreads();
    }
    if (threadIdx.x == 0) out[0] = red[0];
}

// ---------------- launch ----------------
extern "C" void kernel_launch(void* const* d_in, const int* in_sizes, int n_in,
                              void* d_out, int out_size) {
    const float* X  = (const float*)d_in[0];   // [16384, 1024]
    const float* Wi = (const float*)d_in[1];   // [1023, 1025]
    const float* Wl = (const float*)d_in[2];   // [1000, 1024]
    float* out = (float*)d_out;

    __half *xh, *php, *wh, *lh, *s_p;
    float *bias_p, *t_p, *u_p;
    cudaGetSymbolAddress((void**)&xh,   g_Xh);
    cudaGetSymbolAddress((void**)&php,  g_Ph);
    cudaGetSymbolAddress((void**)&wh,   g_Wh);
    cudaGetSymbolAddress((void**)&lh,   g_Lh);
    cudaGetSymbolAddress((void**)&s_p,  g_s);
    cudaGetSymbolAddress((void**)&bias_p, g_bias);
    cudaGetSymbolAddress((void**)&t_p,  g_T);
    cudaGetSymbolAddress((void**)&u_p,  g_U);

    cudaFuncSetAttribute(mma_gemm_kernel<true>,
                         cudaFuncAttributeMaxDynamicSharedMemorySize, DYN_SMEM);
    cudaFuncSetAttribute(mma_gemm_kernel<false>,
                         cudaFuncAttributeMaxDynamicSharedMemorySize, DYN_SMEM);

    // 1. convert X and weights to fp16
    conv_x_kernel<<<(B_SZ * KDIM / 4 + 255) / 256, 256>>>(X, xh);
    repack_w_kernel<<<(KDIM * KDIM + 255) / 256, 256>>>(Wi, wh, bias_p, t_p, u_p);
    repack_l_kernel<<<(KDIM * KDIM + 255) / 256, 256>>>(Wl, lh);

    // 2. GEMM1 + bias + sigmoid-0.5 -> g_s (fp16 centered, ld=1024)
    {
        dim3 grid(8, B_SZ / 128);   // (8, 128)
        mma_gemm_kernel<true><<<grid, 256, DYN_SMEM>>>(
            xh, wh, bias_p, s_p, 1024, 1024);
    }

    // 3. path probs (fp16) + regularizer partial sums
    path_kernel<<<B_SZ / SAMPLES_PER_BLOCK, 256>>>(s_p, php, t_p, u_p);

    // 4. GEMM2: predictions = path @ W_leaf^T -> d_out (fp32, ld=1000)
    {
        dim3 grid(8, B_SZ / 128);
        mma_gemm_kernel<false><<<grid, 256, DYN_SMEM>>>(
            php, lh, nullptr, out, OUT_DIM, OUT_DIM);
    }

    // 5. regularizer scalar -> last output element
    reg_kernel<<<1, 256>>>(t_p, u_p, out + (out_size - 1));
}

// round 14
// speedup vs baseline: 1.8890x; 1.0099x over previous
#include <cuda_runtime.h>
#include <cuda_fp16.h>
#include <cstdint>
#include <math.h>

// ---------------- problem constants ----------------
#define B_SZ      16384
#define KDIM      1024
#define OUT_DIM   1000
#define N_INT     1023
#define DEPTH     10
#define LAMBDA    1e-3f

// ---------------- scratch (device globals) ----------------
__device__ __half g_Xh[(size_t)B_SZ * KDIM];        // X as fp16
__device__ __half g_Ph[(size_t)B_SZ * KDIM];        // path probs fp16
__device__ __half g_Wh[(size_t)KDIM * KDIM];        // W_internal fp16
__device__ __half g_Lh[(size_t)KDIM * KDIM];        // W_leaf fp16
__device__ __half g_s[(size_t)B_SZ * KDIM];         // sigmoid-0.5, fp16 (centered)
__device__ float g_bias[KDIM];
__device__ float g_T[1023];
__device__ float g_U[2046];

// ---------------- PTX helpers (sm_80-class features only) ----------------
__device__ __forceinline__ uint32_t smem_u32(const void* p) {
    uint32_t a;
    asm("{ .reg .u64 t; cvta.to.shared.u64 t, %1; cvt.u32.u64 %0, t; }" : "=r"(a) : "l"(p));
    return a;
}

#define CP_ASYNC16(dst, src) \
    asm volatile("cp.async.cg.shared.global [%0], [%1], 16;" :: "r"(dst), "l"(src))
#define CP_COMMIT() asm volatile("cp.async.commit_group;" ::: "memory")
#define CP_WAIT(n)  asm volatile("cp.async.wait_group %0;" :: "n"(n) : "memory")

#define LDMX4(r0, r1, r2, r3, addr) \
    asm volatile("ldmatrix.sync.aligned.m8n8.x4.shared.b16 {%0,%1,%2,%3}, [%4];" \
        : "=r"(r0), "=r"(r1), "=r"(r2), "=r"(r3) : "r"(addr))

#define MMAF16(d, a, b) \
    asm volatile("mma.sync.aligned.m16n8k16.row.col.f32.f16.f16.f32 " \
        "{%0,%1,%2,%3}, {%4,%5,%6,%7}, {%8,%9}, {%0,%1,%2,%3};" \
        : "+f"((d)[0]), "+f"((d)[1]), "+f"((d)[2]), "+f"((d)[3]) \
        : "r"((a)[0]), "r"((a)[1]), "r"((a)[2]), "r"((a)[3]), \
          "r"((b)[0]), "r"((b)[1]))

// X: fp32 -> fp16
__global__ void conv_x_kernel(const float* __restrict__ src,
                              __half* __restrict__ dst) {
    size_t i = (size_t)blockIdx.x * blockDim.x + threadIdx.x;  // quad index
    float4 v = ((const float4*)src)[i];
    ((__half2*)dst)[2 * i]     = __floats2half2_rn(v.x, v.y);
    ((__half2*)dst)[2 * i + 1] = __floats2half2_rn(v.z, v.w);
}

// W_internal: repack [1023,1025] -> aligned fp16 + fp32 bias; zero T/U
__global__ void repack_w_kernel(const float* __restrict__ Wi,
                                __half* __restrict__ wh,
                                float* __restrict__ bias,
                                float* __restrict__ t, float* __restrict__ u) {
    int idx = blockIdx.x * blockDim.x + threadIdx.x;
    if (idx < KDIM * KDIM) {
        int n = idx >> 10, k = idx & 1023;
        float v = (n < N_INT) ? Wi[(size_t)n * 1025 + 1 + k] : 0.0f;
        wh[idx] = __float2half_rn(v);
    }
    if (idx < KDIM) bias[idx] = (idx < N_INT) ? Wi[(size_t)idx * 1025] : 0.0f;
    if (idx < 1023) t[idx] = 0.0f;
    if (idx < 2046) u[idx] = 0.0f;
}

__global__ void repack_l_kernel(const float* __restrict__ Wl,
                                __half* __restrict__ lh) {
    int idx = blockIdx.x * blockDim.x + threadIdx.x;
    if (idx < KDIM * KDIM) {
        int n = idx >> 10, k = idx & 1023;
        float v = (n < OUT_DIM) ? Wl[(size_t)n * KDIM + k] : 0.0f;
        lh[idx] = __float2half_rn(v);
    }
}

// ---------------- mma.sync GEMM: C[M,N] = A * B^T, pure fp16 ---------------
// CTA tile 128x128, BK=64, 2-stage cp.async ring (R11-proven), 256 threads
// (8 warps 4Mx2N, warp tile 32x64), 2 CTAs/SM. One __syncthreads per chunk;
// prefetch immediately after the barrier (full-chunk latency shadow).
// SIG=true: epilogue sigmoid-0.5 -> fp16 (centered). SIG=false: fp32 out.
#define ROWB        144                   // 128B data + 16B pad (conflict-free)
#define TROWS       128
#define OFF_A       0
#define OFF_B       (TROWS * ROWB)        // 18432
#define STAGE_BYTES (2 * TROWS * ROWB)    // 36864
#define NSTAGE      2
#define NCHUNK      16                    // K=1024 / BK=64
#define DYN_SMEM    (NSTAGE * STAGE_BYTES + 512)

__device__ __forceinline__ void load_stage(
        const __half* __restrict__ A, const __half* __restrict__ B,
        int m0, int n0, int chunk, uint32_t sb, int tid) {
    const int r = tid >> 3;            // 0..31
    const int c = tid & 7;             // 16B eighth of the 128B row
    const int kk = chunk * 64 + c * 8; // fp16 element offset
    const uint32_t doff = (uint32_t)r * ROWB + (uint32_t)c * 16;
#pragma unroll
    for (int h = 0; h < 4; h++) {
        const int rr = r + h * 32;
        const uint32_t d = sb + doff + (uint32_t)(h * 32 * ROWB);
        CP_ASYNC16(d + OFF_A, A + (size_t)(m0 + rr) * KDIM + kk);
        CP_ASYNC16(d + OFF_B, B + (size_t)(n0 + rr) * KDIM + kk);
    }
}

template<bool SIG>
__global__ void __launch_bounds__(256, 2)
mma_gemm_kernel(const __half* __restrict__ A, const __half* __restrict__ B,
                const float* __restrict__ bias, void* __restrict__ Cv,
                int ldc, int nclip) {
    extern __shared__ char sm[];
    const uint32_t s0 = smem_u32(sm);
    float* bias_sh = (float*)(sm + NSTAGE * STAGE_BYTES);

    const int tid  = threadIdx.x;
    const int lane = tid & 31;
    const int wid  = tid >> 5;
    const int wm   = wid & 3;    // 4 M-warps of 32 rows
    const int wn   = wid >> 2;   // 2 N-warps of 64 cols
    const int m0   = blockIdx.y * 128;
    const int n0   = blockIdx.x * 128;

    if (SIG && tid < 128) bias_sh[tid] = bias[n0 + tid];

    float acc[2][8][4];
#pragma unroll
    for (int mi = 0; mi < 2; mi++)
#pragma unroll
        for (int ni = 0; ni < 8; ni++)
#pragma unroll
            for (int j = 0; j < 4; j++) acc[mi][ni][j] = 0.0f;

    // ldmatrix per-thread address components (within a 128B row)
    const uint32_t a_off = (uint32_t)(wm * 32 + (lane & 15)) * ROWB
                         + (uint32_t)(lane >> 4) * 16;
    const uint32_t b_off = (uint32_t)(wn * 64 + ((lane >> 4) & 1) * 8 + (lane & 7)) * ROWB
                         + (uint32_t)((lane >> 3) & 1) * 16;

    // prologue: stage 0
    load_stage(A, B, m0, n0, 0, s0, tid);
    CP_COMMIT();

    for (int s = 0; s < NCHUNK; s++) {
        CP_WAIT(0);          // stage s landed (this thread)
        __syncthreads();     // stage s visible CTA-wide; stage s-1 reads all done

        // prefetch stage s+1 NOW: its buffer was consumed in chunk s-1
        if (s + 1 < NCHUNK) {
            load_stage(A, B, m0, n0, s + 1,
                       s0 + (uint32_t)((s + 1) & 1) * STAGE_BYTES, tid);
            CP_COMMIT();
        }

        const uint32_t sb = s0 + (uint32_t)(s & 1) * STAGE_BYTES;

#pragma unroll
        for (int ks = 0; ks < 4; ks++) {
            uint32_t ar[2][4];
#pragma unroll
            for (int mi = 0; mi < 2; mi++) {
                const uint32_t ao = sb + a_off + (uint32_t)(mi * 16 * ROWB)
                                  + (uint32_t)(ks * 32);
                LDMX4(ar[mi][0], ar[mi][1], ar[mi][2], ar[mi][3], ao + OFF_A);
            }
#pragma unroll
            for (int half = 0; half < 2; half++) {
                uint32_t br[4][2];
#pragma unroll
                for (int p = 0; p < 2; p++) {
                    const int pj = half * 2 + p;
                    const uint32_t bo = sb + b_off + (uint32_t)(pj * 16 * ROWB)
                                      + (uint32_t)(ks * 32);
                    LDMX4(br[2 * p][0], br[2 * p][1], br[2 * p + 1][0], br[2 * p + 1][1],
                          bo + OFF_B);
                }
#pragma unroll
                for (int mi = 0; mi < 2; mi++)
#pragma unroll
                    for (int nj = 0; nj < 4; nj++)
                        MMAF16(acc[mi][half * 4 + nj], ar[mi], br[nj]);
            }
        }
    }

    // epilogue
    const int tr = lane >> 2;
    const int tc = (lane & 3) * 2;
#pragma unroll
    for (int mi = 0; mi < 2; mi++) {
#pragma unroll
        for (int ni = 0; ni < 8; ni++) {
            const int row = m0 + wm * 32 + mi * 16 + tr;
            const int col = n0 + wn * 64 + ni * 8 + tc;
            float v0 = acc[mi][ni][0], v1 = acc[mi][ni][1];
            float v2 = acc[mi][ni][2], v3 = acc[mi][ni][3];
            if (SIG) {
                // centered sigmoid: sigmoid(x) - 0.5, stored fp16
                const float b0 = bias_sh[col - n0];
                const float b1 = bias_sh[col - n0 + 1];
                v0 = 1.0f / (1.0f + expf(-(v0 + b0))) - 0.5f;
                v1 = 1.0f / (1.0f + expf(-(v1 + b1))) - 0.5f;
                v2 = 1.0f / (1.0f + expf(-(v2 + b0))) - 0.5f;
                v3 = 1.0f / (1.0f + expf(-(v3 + b1))) - 0.5f;
                __half* C = (__half*)Cv;
                *(__half2*)&C[(size_t)row * ldc + col]       = __floats2half2_rn(v0, v1);
                *(__half2*)&C[(size_t)(row + 8) * ldc + col] = __floats2half2_rn(v2, v3);
            } else {
                float* C = (float*)Cv;
                if (col < nclip) {  // col even, nclip even -> pair never straddles
                    *(float2*)&C[(size_t)row * ldc + col]       = make_float2(v0, v1);
                    *(float2*)&C[(size_t)(row + 8) * ldc + col] = make_float2(v2, v3);
                }
            }
        }
    }
}

// ---------------- path + regularizer partial sums ----------------
// Two samples interleaved per barrier phase: halves barrier count and doubles
// independent work per phase. g_s holds centered sigmoids (fp16).
#define SAMPLES_PER_BLOCK 8

__global__ void __launch_bounds__(256)
path_kernel(const __half* __restrict__ s_g,
            __half* __restrict__ ph,
            float* __restrict__ gT, float* __restrict__ gU) {
    __shared__ float s_sh[2][1024];
    __shared__ float bufA[2][1024];
    __shared__ float bufB[2][1024];
    __shared__ float Tacc[1023];
    __shared__ float Uacc[2046];

    const int tid = threadIdx.x;
    for (int i = tid; i < 1023; i += 256) Tacc[i] = 0.0f;
    for (int i = tid; i < 2046; i += 256) Uacc[i] = 0.0f;

    const int base = blockIdx.x * SAMPLES_PER_BLOCK;

    for (int s = 0; s < SAMPLES_PER_BLOCK; s += 2) {
        const int b0 = base + s;
        __syncthreads();   // previous pair fully consumed
        // load both samples' centered sigmoids; reconstruct s = 0.5 + c
        for (int i = tid; i < 1024; i += 256) {
            const int smp = i >> 9;          // 0 or 1
            const int j   = i & 511;         // half2 index within sample
            __half2 cv = ((const __half2*)(s_g + (size_t)(b0 + smp) * 1024))[j];
            float2 cf = __half22float2(cv);
            s_sh[smp][2 * j]     = 0.5f + cf.x;
            s_sh[smp][2 * j + 1] = 0.5f + cf.y;
        }
        if (tid < 2) bufA[tid][0] = 1.0f;
        __syncthreads();

        float* cur0 = bufA[0]; float* nxt0 = bufB[0];
        float* cur1 = bufA[1]; float* nxt1 = bufB[1];
        int toff = 0, uoff = 0;

#pragma unroll
        for (int d = 0; d < DEPTH; d++) {
            const int nout = 2 << d;
            const int nbase = (1 << d) - 1;
            // sample 0
            for (int k = tid; k < nout; k += 256) {
                float sv = s_sh[0][nbase + (k >> 1)];
                float lp = (k & 1) ? (1.0f - sv) : sv;
                float nk = cur0[k >> 1] * lp;
                nxt0[k] = nk;
                int p = k >> 1;
                float svp = s_sh[0][nbase + (p >> 1)];
                float lpp = (p & 1) ? (1.0f - svp) : svp;
                Uacc[uoff + k] += lp * (cur0[p >> 1] * lpp);
                if (k < (nout >> 1)) Tacc[toff + k] += nk;
            }
            // sample 1 (same tid owns same indices -> no races with sample 0)
            for (int k = tid; k < nout; k += 256) {
                float sv = s_sh[1][nbase + (k >> 1)];
                float lp = (k & 1) ? (1.0f - sv) : sv;
                float nk = cur1[k >> 1] * lp;
                nxt1[k] = nk;
                int p = k >> 1;
                float svp = s_sh[1][nbase + (p >> 1)];
                float lpp = (p & 1) ? (1.0f - svp) : svp;
                Uacc[uoff + k] += lp * (cur1[p >> 1] * lpp);
                if (k < (nout >> 1)) Tacc[toff + k] += nk;
            }
            __syncthreads();
            toff += nout >> 1;
            uoff += nout;
            float* t;
            t = cur0; cur0 = nxt0; nxt0 = t;
            t = cur1; cur1 = nxt1; nxt1 = t;
        }

        for (int l = tid; l < 1024; l += 256) {
            ph[(size_t)b0 * 1024 + l]       = __float2half_rn(cur0[l]);
            ph[(size_t)(b0 + 1) * 1024 + l] = __float2half_rn(cur1[l]);
        }
    }

    __syncthreads();
    for (int i = tid; i < 1023; i += 256) atomicAdd(&gT[i], Tacc[i]);
    for (int i = tid; i < 2046; i += 256) atomicAdd(&gU[i], Uacc[i]);
}

// ---------------- regularizer scalar ----------------
__global__ void reg_kernel(const float* __restrict__ gT, const float* __restrict__ gU,
                           float* __restrict__ out) {
    float local = 0.0f;
    int toff = 0, uoff = 0;
#pragma unroll
    for (int d = 0; d < DEPTH; d++) {
        const int nout = 2 << d;
        const float factor = LAMBDA * exp2f(-(float)d);
        for (int k = threadIdx.x; k < nout; k += 256) {
            float den = gT[toff + (k >> 1)] + 1e-8f;
            float alpha = gU[uoff + k] / den;
            local += factor * (-0.5f) * (logf(alpha) + logf(1.0f - alpha));
        }
        toff += (1 << d);
        uoff += nout;
    }
    __shared__ float red[256];
    red[threadIdx.x] = local;
    __syncthreads();
    for (int s = 128; s > 0; s >>= 1) {
        if (threadIdx.x < s) red[threadIdx.x] += red[threadIdx.x + s];
        __syncthreads();
    }
    if (threadIdx.x == 0) out[0] = red[0];
}

// ---------------- launch ----------------
extern "C" void kernel_launch(void* const* d_in, const int* in_sizes, int n_in,
                              void* d_out, int out_size) {
    const float* X  = (const float*)d_in[0];   // [16384, 1024]
    const float* Wi = (const float*)d_in[1];   // [1023, 1025]
    const float* Wl = (const float*)d_in[2];   // [1000, 1024]
    float* out = (float*)d_out;

    __half *xh, *php, *wh, *lh, *s_p;
    float *bias_p, *t_p, *u_p;
    cudaGetSymbolAddress((void**)&xh,   g_Xh);
    cudaGetSymbolAddress((void**)&php,  g_Ph);
    cudaGetSymbolAddress((void**)&wh,   g_Wh);
    cudaGetSymbolAddress((void**)&lh,   g_Lh);
    cudaGetSymbolAddress((void**)&s_p,  g_s);
    cudaGetSymbolAddress((void**)&bias_p, g_bias);
    cudaGetSymbolAddress((void**)&t_p,  g_T);
    cudaGetSymbolAddress((void**)&u_p,  g_U);

    cudaFuncSetAttribute(mma_gemm_kernel<true>,
                         cudaFuncAttributeMaxDynamicSharedMemorySize, DYN_SMEM);
    cudaFuncSetAttribute(mma_gemm_kernel<false>,
                         cudaFuncAttributeMaxDynamicSharedMemorySize, DYN_SMEM);

    // 1. convert X and weights to fp16
    conv_x_kernel<<<(B_SZ * KDIM / 4 + 255) / 256, 256>>>(X, xh);
    repack_w_kernel<<<(KDIM * KDIM + 255) / 256, 256>>>(Wi, wh, bias_p, t_p, u_p);
    repack_l_kernel<<<(KDIM * KDIM + 255) / 256, 256>>>(Wl, lh);

    // 2. GEMM1 + bias + sigmoid-0.5 -> g_s (fp16 centered, ld=1024)
    {
        dim3 grid(8, B_SZ / 128);   // (8, 128)
        mma_gemm_kernel<true><<<grid, 256, DYN_SMEM>>>(
            xh, wh, bias_p, s_p, 1024, 1024);
    }

    // 3. path probs (fp16) + regularizer partial sums
    path_kernel<<<B_SZ / SAMPLES_PER_BLOCK, 256>>>(s_p, php, t_p, u_p);

    // 4. GEMM2: predictions = path @ W_leaf^T -> d_out (fp32, ld=1000)
    {
        dim3 grid(8, B_SZ / 128);
        mma_gemm_kernel<false><<<grid, 256, DYN_SMEM>>>(
            php, lh, nullptr, out, OUT_DIM, OUT_DIM);
    }

    // 5. regularizer scalar -> last output element
    reg_kernel<<<1, 256>>>(t_p, u_p, out + (out_size - 1));
}

// round 15
// speedup vs baseline: 1.9281x; 1.0207x over previous
#include <cuda_runtime.h>
#include <cuda_fp16.h>
#include <cstdint>
#include <math.h>

// ---------------- problem constants ----------------
#define B_SZ      16384
#define KDIM      1024
#define OUT_DIM   1000
#define N_INT     1023
#define DEPTH     10
#define LAMBDA    1e-3f

// ---------------- scratch (device globals) ----------------
__device__ __half g_Xh[(size_t)B_SZ * KDIM];        // X as fp16
__device__ __half g_Ph[(size_t)B_SZ * KDIM];        // path probs fp16
__device__ __half g_Wh[(size_t)KDIM * KDIM];        // W_internal fp16
__device__ __half g_Lh[(size_t)KDIM * KDIM];        // W_leaf fp16
__device__ __half g_s[(size_t)B_SZ * KDIM];         // sigmoid-0.5, fp16 (centered)
__device__ float g_bias[KDIM];
__device__ float g_T[1023];
__device__ float g_U[2046];

// ---------------- PTX helpers (sm_80-class features only) ----------------
__device__ __forceinline__ uint32_t smem_u32(const void* p) {
    uint32_t a;
    asm("{ .reg .u64 t; cvta.to.shared.u64 t, %1; cvt.u32.u64 %0, t; }" : "=r"(a) : "l"(p));
    return a;
}

#define CP_ASYNC16(dst, src) \
    asm volatile("cp.async.cg.shared.global [%0], [%1], 16;" :: "r"(dst), "l"(src))
#define CP_COMMIT() asm volatile("cp.async.commit_group;" ::: "memory")
#define CP_WAIT(n)  asm volatile("cp.async.wait_group %0;" :: "n"(n) : "memory")

#define LDMX4(r0, r1, r2, r3, addr) \
    asm volatile("ldmatrix.sync.aligned.m8n8.x4.shared.b16 {%0,%1,%2,%3}, [%4];" \
        : "=r"(r0), "=r"(r1), "=r"(r2), "=r"(r3) : "r"(addr))

#define MMAF16(d, a, b) \
    asm volatile("mma.sync.aligned.m16n8k16.row.col.f32.f16.f16.f32 " \
        "{%0,%1,%2,%3}, {%4,%5,%6,%7}, {%8,%9}, {%0,%1,%2,%3};" \
        : "+f"((d)[0]), "+f"((d)[1]), "+f"((d)[2]), "+f"((d)[3]) \
        : "r"((a)[0]), "r"((a)[1]), "r"((a)[2]), "r"((a)[3]), \
          "r"((b)[0]), "r"((b)[1]))

// X: fp32 -> fp16
__global__ void conv_x_kernel(const float* __restrict__ src,
                              __half* __restrict__ dst) {
    size_t i = (size_t)blockIdx.x * blockDim.x + threadIdx.x;  // quad index
    float4 v = ((const float4*)src)[i];
    ((__half2*)dst)[2 * i]     = __floats2half2_rn(v.x, v.y);
    ((__half2*)dst)[2 * i + 1] = __floats2half2_rn(v.z, v.w);
}

// W_internal: repack [1023,1025] -> aligned fp16 + fp32 bias; zero T/U
__global__ void repack_w_kernel(const float* __restrict__ Wi,
                                __half* __restrict__ wh,
                                float* __restrict__ bias,
                                float* __restrict__ t, float* __restrict__ u) {
    int idx = blockIdx.x * blockDim.x + threadIdx.x;
    if (idx < KDIM * KDIM) {
        int n = idx >> 10, k = idx & 1023;
        float v = (n < N_INT) ? Wi[(size_t)n * 1025 + 1 + k] : 0.0f;
        wh[idx] = __float2half_rn(v);
    }
    if (idx < KDIM) bias[idx] = (idx < N_INT) ? Wi[(size_t)idx * 1025] : 0.0f;
    if (idx < 1023) t[idx] = 0.0f;
    if (idx < 2046) u[idx] = 0.0f;
}

__global__ void repack_l_kernel(const float* __restrict__ Wl,
                                __half* __restrict__ lh) {
    int idx = blockIdx.x * blockDim.x + threadIdx.x;
    if (idx < KDIM * KDIM) {
        int n = idx >> 10, k = idx & 1023;
        float v = (n < OUT_DIM) ? Wl[(size_t)n * KDIM + k] : 0.0f;
        lh[idx] = __float2half_rn(v);
    }
}

// ---------------- mma.sync GEMM: C[M,N] = A * B^T, pure fp16 ---------------
// CTA tile 128x128, BK=64, 2-stage cp.async ring, 256 threads (8 warps 4Mx2N,
// warp tile 32x64), 2 CTAs/SM. One __syncthreads per chunk; prefetch right
// after the barrier. SIG: sigmoid-0.5 -> fp16 centered. else fp32 out.
#define ROWB        144                   // 128B data + 16B pad (conflict-free)
#define TROWS       128
#define OFF_A       0
#define OFF_B       (TROWS * ROWB)        // 18432
#define STAGE_BYTES (2 * TROWS * ROWB)    // 36864
#define NSTAGE      2
#define NCHUNK      16                    // K=1024 / BK=64
#define DYN_SMEM    (NSTAGE * STAGE_BYTES + 512)

__device__ __forceinline__ void load_stage(
        const __half* __restrict__ A, const __half* __restrict__ B,
        int m0, int n0, int chunk, uint32_t sb, int tid) {
    const int r = tid >> 3;            // 0..31
    const int c = tid & 7;             // 16B eighth of the 128B row
    const int kk = chunk * 64 + c * 8; // fp16 element offset
    const uint32_t doff = (uint32_t)r * ROWB + (uint32_t)c * 16;
#pragma unroll
    for (int h = 0; h < 4; h++) {
        const int rr = r + h * 32;
        const uint32_t d = sb + doff + (uint32_t)(h * 32 * ROWB);
        CP_ASYNC16(d + OFF_A, A + (size_t)(m0 + rr) * KDIM + kk);
        CP_ASYNC16(d + OFF_B, B + (size_t)(n0 + rr) * KDIM + kk);
    }
}

template<bool SIG>
__global__ void __launch_bounds__(256, 2)
mma_gemm_kernel(const __half* __restrict__ A, const __half* __restrict__ B,
                const float* __restrict__ bias, void* __restrict__ Cv,
                int ldc, int nclip) {
    extern __shared__ char sm[];
    const uint32_t s0 = smem_u32(sm);
    float* bias_sh = (float*)(sm + NSTAGE * STAGE_BYTES);

    const int tid  = threadIdx.x;
    const int lane = tid & 31;
    const int wid  = tid >> 5;
    const int wm   = wid & 3;    // 4 M-warps of 32 rows
    const int wn   = wid >> 2;   // 2 N-warps of 64 cols
    const int m0   = blockIdx.y * 128;
    const int n0   = blockIdx.x * 128;

    if (SIG && tid < 128) bias_sh[tid] = bias[n0 + tid];

    float acc[2][8][4];
#pragma unroll
    for (int mi = 0; mi < 2; mi++)
#pragma unroll
        for (int ni = 0; ni < 8; ni++)
#pragma unroll
            for (int j = 0; j < 4; j++) acc[mi][ni][j] = 0.0f;

    const uint32_t a_off = (uint32_t)(wm * 32 + (lane & 15)) * ROWB
                         + (uint32_t)(lane >> 4) * 16;
    const uint32_t b_off = (uint32_t)(wn * 64 + ((lane >> 4) & 1) * 8 + (lane & 7)) * ROWB
                         + (uint32_t)((lane >> 3) & 1) * 16;

    load_stage(A, B, m0, n0, 0, s0, tid);
    CP_COMMIT();

    for (int s = 0; s < NCHUNK; s++) {
        CP_WAIT(0);
        __syncthreads();

        if (s + 1 < NCHUNK) {
            load_stage(A, B, m0, n0, s + 1,
                       s0 + (uint32_t)((s + 1) & 1) * STAGE_BYTES, tid);
            CP_COMMIT();
        }

        const uint32_t sb = s0 + (uint32_t)(s & 1) * STAGE_BYTES;

#pragma unroll
        for (int ks = 0; ks < 4; ks++) {
            uint32_t ar[2][4];
#pragma unroll
            for (int mi = 0; mi < 2; mi++) {
                const uint32_t ao = sb + a_off + (uint32_t)(mi * 16 * ROWB)
                                  + (uint32_t)(ks * 32);
                LDMX4(ar[mi][0], ar[mi][1], ar[mi][2], ar[mi][3], ao + OFF_A);
            }
#pragma unroll
            for (int half = 0; half < 2; half++) {
                uint32_t br[4][2];
#pragma unroll
                for (int p = 0; p < 2; p++) {
                    const int pj = half * 2 + p;
                    const uint32_t bo = sb + b_off + (uint32_t)(pj * 16 * ROWB)
                                      + (uint32_t)(ks * 32);
                    LDMX4(br[2 * p][0], br[2 * p][1], br[2 * p + 1][0], br[2 * p + 1][1],
                          bo + OFF_B);
                }
#pragma unroll
                for (int mi = 0; mi < 2; mi++)
#pragma unroll
                    for (int nj = 0; nj < 4; nj++)
                        MMAF16(acc[mi][half * 4 + nj], ar[mi], br[nj]);
            }
        }
    }

    // epilogue
    const int tr = lane >> 2;
    const int tc = (lane & 3) * 2;
#pragma unroll
    for (int mi = 0; mi < 2; mi++) {
#pragma unroll
        for (int ni = 0; ni < 8; ni++) {
            const int row = m0 + wm * 32 + mi * 16 + tr;
            const int col = n0 + wn * 64 + ni * 8 + tc;
            float v0 = acc[mi][ni][0], v1 = acc[mi][ni][1];
            float v2 = acc[mi][ni][2], v3 = acc[mi][ni][3];
            if (SIG) {
                const float b0 = bias_sh[col - n0];
                const float b1 = bias_sh[col - n0 + 1];
                v0 = 1.0f / (1.0f + __expf(-(v0 + b0))) - 0.5f;
                v1 = 1.0f / (1.0f + __expf(-(v1 + b1))) - 0.5f;
                v2 = 1.0f / (1.0f + __expf(-(v2 + b0))) - 0.5f;
                v3 = 1.0f / (1.0f + __expf(-(v3 + b1))) - 0.5f;
                __half* C = (__half*)Cv;
                *(__half2*)&C[(size_t)row * ldc + col]       = __floats2half2_rn(v0, v1);
                *(__half2*)&C[(size_t)(row + 8) * ldc + col] = __floats2half2_rn(v2, v3);
            } else {
                float* C = (float*)Cv;
                if (col < nclip) {
                    *(float2*)&C[(size_t)row * ldc + col]       = make_float2(v0, v1);
                    *(float2*)&C[(size_t)(row + 8) * ldc + col] = make_float2(v2, v3);
                }
            }
        }
    }
}

// ---------------- path + regularizer partial sums ----------------
// Pair-based processing: thread owning pair j computes both children with
// nk1 = cur - nk0 and u1 = pn - u0 (halves iterations and sv loads).
// Two samples interleaved per barrier phase.
#define SAMPLES_PER_BLOCK 8

__global__ void __launch_bounds__(256)
path_kernel(const __half* __restrict__ s_g,
            __half* __restrict__ ph,
            float* __restrict__ gT, float* __restrict__ gU) {
    __shared__ float s_sh[2][1024];
    __shared__ float bufA[2][1024];
    __shared__ float bufB[2][1024];
    __shared__ float Tacc[1023];
    __shared__ float Uacc[2046];

    const int tid = threadIdx.x;
    for (int i = tid; i < 1023; i += 256) Tacc[i] = 0.0f;
    for (int i = tid; i < 2046; i += 256) Uacc[i] = 0.0f;

    const int base = blockIdx.x * SAMPLES_PER_BLOCK;

    for (int s = 0; s < SAMPLES_PER_BLOCK; s += 2) {
        const int b0 = base + s;
        __syncthreads();   // previous pair of samples fully consumed
        for (int i = tid; i < 1024; i += 256) {
            const int smp = i >> 9;
            const int j   = i & 511;
            __half2 cv = ((const __half2*)(s_g + (size_t)(b0 + smp) * 1024))[j];
            float2 cf = __half22float2(cv);
            s_sh[smp][2 * j]     = 0.5f + cf.x;
            s_sh[smp][2 * j + 1] = 0.5f + cf.y;
        }
        if (tid < 2) bufA[tid][0] = 1.0f;
        __syncthreads();

        float* cur0 = bufA[0]; float* nxt0 = bufB[0];
        float* cur1 = bufA[1]; float* nxt1 = bufB[1];
        int toff = 0, uoff = 0;

#pragma unroll
        for (int d = 0; d < DEPTH; d++) {
            const int npair = 1 << d;          // pairs at this level
            const int nbase = npair - 1;       // level-d node base
#pragma unroll 1
            for (int j = tid; j < npair; j += 256) {
                // sample 0
                {
                    float sv = s_sh[0][nbase + j];
                    float cj = cur0[j];
                    float nk0 = cj * sv;
                    float nk1 = cj - nk0;
                    nxt0[2 * j]     = nk0;
                    nxt0[2 * j + 1] = nk1;
                    float svp = s_sh[0][nbase + (j >> 1)];
                    float lpp = (j & 1) ? (1.0f - svp) : svp;
                    float pn  = cur0[j >> 1] * lpp;
                    float u0  = sv * pn;
                    Uacc[uoff + 2 * j]     += u0;
                    Uacc[uoff + 2 * j + 1] += pn - u0;
                    if (2 * j < npair)     Tacc[toff + 2 * j]     += nk0;
                    if (2 * j + 1 < npair) Tacc[toff + 2 * j + 1] += nk1;
                }
                // sample 1 (same ownership -> race-free)
                {
                    float sv = s_sh[1][nbase + j];
                    float cj = cur1[j];
                    float nk0 = cj * sv;
                    float nk1 = cj - nk0;
                    nxt1[2 * j]     = nk0;
                    nxt1[2 * j + 1] = nk1;
                    float svp = s_sh[1][nbase + (j >> 1)];
                    float lpp = (j & 1) ? (1.0f - svp) : svp;
                    float pn  = cur1[j >> 1] * lpp;
                    float u0  = sv * pn;
                    Uacc[uoff + 2 * j]     += u0;
                    Uacc[uoff + 2 * j + 1] += pn - u0;
                    if (2 * j < npair)     Tacc[toff + 2 * j]     += nk0;
                    if (2 * j + 1 < npair) Tacc[toff + 2 * j + 1] += nk1;
                }
            }
            __syncthreads();
            toff += npair;
            uoff += 2 * npair;
            float* t;
            t = cur0; cur0 = nxt0; nxt0 = t;
            t = cur1; cur1 = nxt1; nxt1 = t;
        }

        for (int l = tid; l < 1024; l += 256) {
            ph[(size_t)b0 * 1024 + l]       = __float2half_rn(cur0[l]);
            ph[(size_t)(b0 + 1) * 1024 + l] = __float2half_rn(cur1[l]);
        }
    }

    __syncthreads();
    for (int i = tid; i < 1023; i += 256) atomicAdd(&gT[i], Tacc[i]);
    for (int i = tid; i < 2046; i += 256) atomicAdd(&gU[i], Uacc[i]);
}

// ---------------- regularizer scalar ----------------
__global__ void reg_kernel(const float* __restrict__ gT, const float* __restrict__ gU,
                           float* __restrict__ out) {
    float local = 0.0f;
    int toff = 0, uoff = 0;
#pragma unroll
    for (int d = 0; d < DEPTH; d++) {
        const int nout = 2 << d;
        const float factor = LAMBDA * exp2f(-(float)d);
        for (int k = threadIdx.x; k < nout; k += 256) {
            float den = gT[toff + (k >> 1)] + 1e-8f;
            float alpha = gU[uoff + k] / den;
            local += factor * (-0.5f) * (logf(alpha) + logf(1.0f - alpha));
        }
        toff += (1 << d);
        uoff += nout;
    }
    __shared__ float red[256];
    red[threadIdx.x] = local;
    __syncthreads();
    for (int s = 128; s > 0; s >>= 1) {
        if (threadIdx.x < s) red[threadIdx.x] += red[threadIdx.x + s];
        __syncthreads();
    }
    if (threadIdx.x == 0) out[0] = red[0];
}

// ---------------- launch ----------------
extern "C" void kernel_launch(void* const* d_in, const int* in_sizes, int n_in,
                              void* d_out, int out_size) {
    const float* X  = (const float*)d_in[0];   // [16384, 1024]
    const float* Wi = (const float*)d_in[1];   // [1023, 1025]
    const float* Wl = (const float*)d_in[2];   // [1000, 1024]
    float* out = (float*)d_out;

    __half *xh, *php, *wh, *lh, *s_p;
    float *bias_p, *t_p, *u_p;
    cudaGetSymbolAddress((void**)&xh,   g_Xh);
    cudaGetSymbolAddress((void**)&php,  g_Ph);
    cudaGetSymbolAddress((void**)&wh,   g_Wh);
    cudaGetSymbolAddress((void**)&lh,   g_Lh);
    cudaGetSymbolAddress((void**)&s_p,  g_s);
    cudaGetSymbolAddress((void**)&bias_p, g_bias);
    cudaGetSymbolAddress((void**)&t_p,  g_T);
    cudaGetSymbolAddress((void**)&u_p,  g_U);

    cudaFuncSetAttribute(mma_gemm_kernel<true>,
                         cudaFuncAttributeMaxDynamicSharedMemorySize, DYN_SMEM);
    cudaFuncSetAttribute(mma_gemm_kernel<false>,
                         cudaFuncAttributeMaxDynamicSharedMemorySize, DYN_SMEM);

    // 1. convert X and weights to fp16
    conv_x_kernel<<<(B_SZ * KDIM / 4 + 255) / 256, 256>>>(X, xh);
    repack_w_kernel<<<(KDIM * KDIM + 255) / 256, 256>>>(Wi, wh, bias_p, t_p, u_p);
    repack_l_kernel<<<(KDIM * KDIM + 255) / 256, 256>>>(Wl, lh);

    // 2. GEMM1 + bias + sigmoid-0.5 -> g_s (fp16 centered, ld=1024)
    {
        dim3 grid(8, B_SZ / 128);   // (8, 128)
        mma_gemm_kernel<true><<<grid, 256, DYN_SMEM>>>(
            xh, wh, bias_p, s_p, 1024, 1024);
    }

    // 3. path probs (fp16) + regularizer partial sums
    path_kernel<<<B_SZ / SAMPLES_PER_BLOCK, 256>>>(s_p, php, t_p, u_p);

    // 4. GEMM2: predictions = path @ W_leaf^T -> d_out (fp32, ld=1000)
    {
        dim3 grid(8, B_SZ / 128);
        mma_gemm_kernel<false><<<grid, 256, DYN_SMEM>>>(
            php, lh, nullptr, out, OUT_DIM, OUT_DIM);
    }

    // 5. regularizer scalar -> last output element
    reg_kernel<<<1, 256>>>(t_p, u_p, out + (out_size - 1));
}